// round 2
// baseline (speedup 1.0000x reference)
#include <cuda_runtime.h>
#include <cuda_bf16.h>
#include <math.h>

// Problem constants
#define B_  8
#define C_  128
#define H_  64
#define W_  64
#define O_  128
#define K2_ 9
#define E_  1152   // C_*K2_

// Scratch (device globals; no allocation allowed)
__device__ float g_xT[B_*H_*W_*C_];        // NHWC, 16.8 MB
__device__ float g_offmask[B_*H_*W_*27];   // per-pixel: 18 offsets + 9 sigmoided masks

// ---------------------------------------------------------------------------
// Kernel A: NCHW -> NHWC transpose
// ---------------------------------------------------------------------------
__global__ void transpose_kernel(const float* __restrict__ x) {
    int idx = blockIdx.x * blockDim.x + threadIdx.x;
    if (idx >= B_*H_*W_*C_) return;
    int c  = idx & 127;
    int t  = idx >> 7;
    int xw = t & 63; t >>= 6;
    int y  = t & 63; t >>= 6;
    int b  = t;
    g_xT[idx] = x[((b*C_ + c)*H_ + y)*W_ + xw];
}

// ---------------------------------------------------------------------------
// Kernel B: offset + mask conv (27 output channels), one block per (b,row)
// smem: x_s[3][64][129] + w_s[1152][28] (+16 pad)
// ---------------------------------------------------------------------------
#define XS_ROW 129
#define WS_OC  28
#define SMEM_B_FLOATS (3*64*XS_ROW + E_*WS_OC + 16)
__global__ void __launch_bounds__(256) offmask_kernel(
    const float* __restrict__ offw, const float* __restrict__ offb,
    const float* __restrict__ maskw, const float* __restrict__ maskb) {
    extern __shared__ float sm[];
    float* x_s = sm;                       // 3*64*129 = 24768 floats
    float* w_s = sm + 3*64*XS_ROW;         // 1152*28  = 32256 floats (+16 pad)
    int b   = blockIdx.x >> 6;
    int row = blockIdx.x & 63;
    int t   = threadIdx.x;

    // stage 3 input rows (zero-padded in y)
    for (int idx = t; idx < 3*64*128; idx += 256) {
        int c  = idx & 127;
        int xp = (idx >> 7) & 63;
        int ki = idx >> 13;
        int y  = row + ki - 1;
        float v = 0.f;
        if (y >= 0 && y < H_) v = g_xT[((b*H_ + y)*W_ + xp)*C_ + c];
        x_s[(ki*64 + xp)*XS_ROW + c] = v;
    }
    // stage weights: w_s[e*28 + oc], e = k2*128 + c
    for (int idx = t; idx < E_*WS_OC; idx += 256) {
        int oc = idx % WS_OC;
        int e  = idx / WS_OC;
        int k2 = e >> 7;
        int c  = e & 127;
        float v = 0.f;
        if (oc < 18)      v = offw[oc*E_ + c*K2_ + k2];
        else if (oc < 27) v = maskw[(oc-18)*E_ + c*K2_ + k2];
        w_s[idx] = v;
    }
    __syncthreads();

    int q  = t & 7;    // oc quad: oc0 = q*4; q==7 -> oc 28..31, all unused: skip
    int pl = t >> 3;   // 0..31: pixel within half-row
    if (q < 7) {
        #pragma unroll
        for (int pass = 0; pass < 2; pass++) {
            int wo = pass*32 + pl;
            float a0 = 0.f, a1 = 0.f, a2 = 0.f, a3 = 0.f;
            #pragma unroll
            for (int ki = 0; ki < 3; ki++) {
                #pragma unroll
                for (int kj = 0; kj < 3; kj++) {
                    int xp = wo + kj - 1;
                    if (xp < 0 || xp >= W_) continue;
                    const float* xr = &x_s[(ki*64 + xp)*XS_ROW];
                    const float* wr = &w_s[((ki*3 + kj)*128)*WS_OC + q*4];
                    #pragma unroll 4
                    for (int c = 0; c < 128; c++) {
                        float xv = xr[c];
                        float4 wv = *(const float4*)(wr + c*WS_OC);
                        a0 = fmaf(xv, wv.x, a0);
                        a1 = fmaf(xv, wv.y, a1);
                        a2 = fmaf(xv, wv.z, a2);
                        a3 = fmaf(xv, wv.w, a3);
                    }
                }
            }
            int pix = (b*H_ + row)*W_ + wo;
            float accs[4] = {a0, a1, a2, a3};
            #pragma unroll
            for (int j = 0; j < 4; j++) {
                int oc = q*4 + j;
                if (oc >= 27) break;
                float v = accs[j];
                if (oc < 18) {
                    v += offb[oc];
                } else {
                    v += maskb[oc - 18];
                    v = 1.f / (1.f + expf(-v));   // sigmoid
                }
                g_offmask[pix*27 + oc] = v;
            }
        }
    }
}

// ---------------------------------------------------------------------------
// Kernel C: main deformable conv. One block = 32 output pixels (half row).
// Phase 1: cols[32][1152] in smem via bilinear sampling from g_xT (NHWC).
// Phase 2: GEMM out[32][128] = cols @ weight^T, streaming weight in 64-chunks.
// ---------------------------------------------------------------------------
#define CS 1153          // cols row stride (odd -> conflict-free)
#define WSTR 132         // w chunk row stride (mult of 4, conflict-free stores)
__global__ void __launch_bounds__(256) dcn_main_kernel(
    const float* __restrict__ weight, float* __restrict__ out) {
    extern __shared__ float sm[];
    float* cols = sm;                 // 32*1153 = 36896 floats
    float* w_s  = sm + 32*CS;         // 64*132  = 8448 floats
    int bi   = blockIdx.x;            // 1024 blocks
    int half = bi & 1;
    int row  = (bi >> 1) & 63;
    int b    = bi >> 7;
    int wo0  = half * 32;
    int t    = threadIdx.x;
    int lane = t & 31;
    int warp = t >> 5;

    // ---- Phase 1: sample cols ----
    const float4* xb4 = (const float4*)g_xT + (size_t)b * H_ * W_ * (C_/4);
    for (int task = warp; task < 32*K2_; task += 8) {
        int p  = task / K2_;
        int k2 = task - p*K2_;
        int wo = wo0 + p;
        int pix = (b*H_ + row)*W_ + wo;
        float offy = g_offmask[pix*27 + 2*k2];
        float offx = g_offmask[pix*27 + 2*k2 + 1];
        float m    = g_offmask[pix*27 + 18 + k2];
        int ki = k2 / 3, kj = k2 - ki*3;
        float py = (float)(row - 1 + ki) + offy;
        float px = (float)(wo  - 1 + kj) + offx;
        float y0f = floorf(py), x0f = floorf(px);
        float ly = py - y0f, lx = px - x0f;
        int y0 = (int)y0f, x0 = (int)x0f;
        float w00 = (1.f-ly)*(1.f-lx)*m;
        float w01 = (1.f-ly)*lx*m;
        float w10 = ly*(1.f-lx)*m;
        float w11 = ly*lx*m;
        bool vy0 = (y0   >= 0) && (y0   < H_);
        bool vy1 = (y0+1 >= 0) && (y0+1 < H_);
        bool vx0 = (x0   >= 0) && (x0   < W_);
        bool vx1 = (x0+1 >= 0) && (x0+1 < W_);
        float4 zero = make_float4(0.f,0.f,0.f,0.f);
        float4 v00 = (vy0 && vx0) ? xb4[(y0*W_     + x0    )*32 + lane] : zero;
        float4 v01 = (vy0 && vx1) ? xb4[(y0*W_     + x0 + 1)*32 + lane] : zero;
        float4 v10 = (vy1 && vx0) ? xb4[((y0+1)*W_ + x0    )*32 + lane] : zero;
        float4 v11 = (vy1 && vx1) ? xb4[((y0+1)*W_ + x0 + 1)*32 + lane] : zero;
        float r0 = w00*v00.x + w01*v01.x + w10*v10.x + w11*v11.x;
        float r1 = w00*v00.y + w01*v01.y + w10*v10.y + w11*v11.y;
        float r2 = w00*v00.z + w01*v01.z + w10*v10.z + w11*v11.z;
        float r3 = w00*v00.w + w01*v01.w + w10*v10.w + w11*v11.w;
        int c0 = lane*4;
        float* cr = &cols[p*CS + k2];
        cr[(c0+0)*K2_] = r0;
        cr[(c0+1)*K2_] = r1;
        cr[(c0+2)*K2_] = r2;
        cr[(c0+3)*K2_] = r3;
    }
    __syncthreads();

    // ---- Phase 2: GEMM ----
    int toc = t >> 3;   // 0..31 -> oc0 = toc*4
    int tp  = t & 7;    // 0..7  -> p0  = tp*4
    int oc0 = toc * 4;
    int p0  = tp * 4;
    float acc[4][4];
    #pragma unroll
    for (int j = 0; j < 4; j++)
        #pragma unroll
        for (int qq = 0; qq < 4; qq++) acc[j][qq] = 0.f;

    for (int ch = 0; ch < E_/64; ch++) {
        int i0 = ch * 64;
        // load weight chunk: w_s[kk*132 + oc] = weight[oc*1152 + i0 + kk]
        for (int idx = t; idx < 64*128; idx += 256) {
            int oc = idx >> 6;
            int kk = idx & 63;
            w_s[kk*WSTR + oc] = weight[oc*E_ + i0 + kk];
        }
        __syncthreads();
        #pragma unroll 4
        for (int kk = 0; kk < 64; kk++) {
            float a0 = cols[(p0+0)*CS + i0 + kk];
            float a1 = cols[(p0+1)*CS + i0 + kk];
            float a2 = cols[(p0+2)*CS + i0 + kk];
            float a3 = cols[(p0+3)*CS + i0 + kk];
            float4 bv = *(const float4*)&w_s[kk*WSTR + oc0];
            acc[0][0] = fmaf(a0, bv.x, acc[0][0]);
            acc[0][1] = fmaf(a0, bv.y, acc[0][1]);
            acc[0][2] = fmaf(a0, bv.z, acc[0][2]);
            acc[0][3] = fmaf(a0, bv.w, acc[0][3]);
            acc[1][0] = fmaf(a1, bv.x, acc[1][0]);
            acc[1][1] = fmaf(a1, bv.y, acc[1][1]);
            acc[1][2] = fmaf(a1, bv.z, acc[1][2]);
            acc[1][3] = fmaf(a1, bv.w, acc[1][3]);
            acc[2][0] = fmaf(a2, bv.x, acc[2][0]);
            acc[2][1] = fmaf(a2, bv.y, acc[2][1]);
            acc[2][2] = fmaf(a2, bv.z, acc[2][2]);
            acc[2][3] = fmaf(a2, bv.w, acc[2][3]);
            acc[3][0] = fmaf(a3, bv.x, acc[3][0]);
            acc[3][1] = fmaf(a3, bv.y, acc[3][1]);
            acc[3][2] = fmaf(a3, bv.z, acc[3][2]);
            acc[3][3] = fmaf(a3, bv.w, acc[3][3]);
        }
        __syncthreads();
    }

    // ---- epilogue: NCHW output ----
    #pragma unroll
    for (int qq = 0; qq < 4; qq++) {
        int oc = oc0 + qq;
        float* orow = out + ((size_t)(b*O_ + oc)*H_ + row)*W_ + wo0 + p0;
        #pragma unroll
        for (int j = 0; j < 4; j++) orow[j] = acc[j][qq];
    }
}

// ---------------------------------------------------------------------------
extern "C" void kernel_launch(void* const* d_in, const int* in_sizes, int n_in,
                              void* d_out, int out_size) {
    const float* x      = (const float*)d_in[0];
    const float* weight = (const float*)d_in[1];
    const float* offw   = (const float*)d_in[2];
    const float* offb   = (const float*)d_in[3];
    const float* maskw  = (const float*)d_in[4];
    const float* maskb  = (const float*)d_in[5];
    float* out = (float*)d_out;

    static bool attr_set = false;
    if (!attr_set) {
        cudaFuncSetAttribute(offmask_kernel,
            cudaFuncAttributeMaxDynamicSharedMemorySize,
            SMEM_B_FLOATS * (int)sizeof(float));
        cudaFuncSetAttribute(dcn_main_kernel,
            cudaFuncAttributeMaxDynamicSharedMemorySize,
            (32*CS + 64*WSTR) * (int)sizeof(float));
        attr_set = true;
    }

    // A: transpose x -> NHWC
    transpose_kernel<<<(B_*H_*W_*C_)/256, 256>>>(x);
    // B: offset + mask conv
    offmask_kernel<<<B_*H_, 256, SMEM_B_FLOATS*sizeof(float)>>>(
        offw, offb, maskw, maskb);
    // C: main deformable conv
    dcn_main_kernel<<<B_*H_*2, 256, (32*CS + 64*WSTR)*sizeof(float)>>>(
        weight, out);
}

// round 6
// speedup vs baseline: 1.5985x; 1.5985x over previous
#include <cuda_runtime.h>
#include <cuda_bf16.h>
#include <math.h>
#include <stdint.h>

// Problem constants
#define B_  8
#define C_  128
#define H_  64
#define W_  64
#define O_  128
#define K2_ 9
#define E_  1152   // C_*K2_

// Scratch (device globals; no allocation allowed)
__device__ float g_xT[B_*H_*W_*C_];          // NHWC, 16.8 MB
__device__ float g_offmask[B_*H_*W_*27];     // 18 offsets + 9 sigmoided masks per pixel
__device__ uint32_t g_whi[K2_*O_*C_/2];      // weight hi split, bf16x2, [k2][oc][c/2]
__device__ uint32_t g_wlo[K2_*O_*C_/2];      // weight lo split

// ===========================================================================
// Helpers (baseline PTX only: ldmatrix + mma.sync, no tcgen05)
// ===========================================================================
__device__ __forceinline__ uint32_t smem_u32(const void* p) {
    uint32_t a;
    asm("{ .reg .u64 t; cvta.to.shared.u64 t, %1; cvt.u32.u64 %0, t; }"
        : "=r"(a) : "l"(p));
    return a;
}
__device__ __forceinline__ void ldsm4(uint32_t* r, uint32_t addr) {
    asm volatile("ldmatrix.sync.aligned.m8n8.x4.shared.b16 {%0,%1,%2,%3}, [%4];"
        : "=r"(r[0]), "=r"(r[1]), "=r"(r[2]), "=r"(r[3]) : "r"(addr));
}
__device__ __forceinline__ void ldsm2(uint32_t* r, uint32_t addr) {
    asm volatile("ldmatrix.sync.aligned.m8n8.x2.shared.b16 {%0,%1}, [%2];"
        : "=r"(r[0]), "=r"(r[1]) : "r"(addr));
}
__device__ __forceinline__ void mma16816(float* c, const uint32_t* a, const uint32_t* b) {
    asm volatile(
        "mma.sync.aligned.m16n8k16.row.col.f32.bf16.bf16.f32 "
        "{%0,%1,%2,%3}, {%4,%5,%6,%7}, {%8,%9}, {%0,%1,%2,%3};"
        : "+f"(c[0]), "+f"(c[1]), "+f"(c[2]), "+f"(c[3])
        : "r"(a[0]), "r"(a[1]), "r"(a[2]), "r"(a[3]), "r"(b[0]), "r"(b[1]));
}
__device__ __forceinline__ uint32_t packbf(__nv_bfloat16 a, __nv_bfloat16 b) {
    __nv_bfloat162 t(a, b);
    return *(uint32_t*)&t;
}

// ===========================================================================
// Kernel A: NCHW -> NHWC transpose
// ===========================================================================
__global__ void transpose_kernel(const float* __restrict__ x) {
    int idx = blockIdx.x * blockDim.x + threadIdx.x;
    if (idx >= B_*H_*W_*C_) return;
    int c  = idx & 127;
    int t  = idx >> 7;
    int xw = t & 63; t >>= 6;
    int y  = t & 63; t >>= 6;
    int b  = t;
    g_xT[idx] = x[((b*C_ + c)*H_ + y)*W_ + xw];
}

// ===========================================================================
// Kernel A2: weight hi/lo split into [k2][oc][c] bf16x2 layout
// ===========================================================================
__global__ void wsplit_kernel(const float* __restrict__ w) {
    int i2 = blockIdx.x * blockDim.x + threadIdx.x;   // u32 pairs
    if (i2 >= K2_*O_*C_/2) return;
    int cpair = i2 & 63;
    int oc    = (i2 >> 6) & 127;
    int k2    = i2 >> 13;
    int c = cpair * 2;
    float v0 = w[oc*E_ + c*K2_ + k2];
    float v1 = w[oc*E_ + (c+1)*K2_ + k2];
    __nv_bfloat16 h0 = __float2bfloat16(v0);
    __nv_bfloat16 h1 = __float2bfloat16(v1);
    __nv_bfloat16 l0 = __float2bfloat16(v0 - __bfloat162float(h0));
    __nv_bfloat16 l1 = __float2bfloat16(v1 - __bfloat162float(h1));
    g_whi[i2] = packbf(h0, h1);
    g_wlo[i2] = packbf(l0, l1);
}

// ===========================================================================
// Kernel B: offset + mask conv (27 out channels), one block per (b,row)
// 2 pixels per thread per weight load. x_s row 192 is a zero row for
// out-of-range columns. w_s offset rounded up to 16B alignment (float4!).
// ===========================================================================
#define XS_ROW 129
#define WS_OC  28
#define WS_OFF 24900                        // ((193*129=24897) rounded up to %4==0)
#define SMEM_B_FLOATS (WS_OFF + E_*WS_OC + 16)
__global__ void __launch_bounds__(256) offmask_kernel(
    const float* __restrict__ offw, const float* __restrict__ offb,
    const float* __restrict__ maskw, const float* __restrict__ maskb) {
    extern __shared__ float sm[];
    float* x_s = sm;                          // 193*129 floats (row 192 = zeros)
    float* w_s = sm + WS_OFF;                 // 1152*28 floats, 16B-aligned
    int b   = blockIdx.x >> 6;
    int row = blockIdx.x & 63;
    int t   = threadIdx.x;

    for (int idx = t; idx < 3*64*128; idx += 256) {
        int c  = idx & 127;
        int xp = (idx >> 7) & 63;
        int ki = idx >> 13;
        int y  = row + ki - 1;
        float v = 0.f;
        if (y >= 0 && y < H_) v = g_xT[((b*H_ + y)*W_ + xp)*C_ + c];
        x_s[(ki*64 + xp)*XS_ROW + c] = v;
    }
    for (int idx = t; idx < XS_ROW; idx += 256)     // zero row
        x_s[192*XS_ROW + idx] = 0.f;
    for (int idx = t; idx < E_*WS_OC; idx += 256) {
        int oc = idx % WS_OC;
        int e  = idx / WS_OC;
        int k2 = e >> 7;
        int c  = e & 127;
        float v = 0.f;
        if (oc < 18)      v = offw[oc*E_ + c*K2_ + k2];
        else if (oc < 27) v = maskw[(oc-18)*E_ + c*K2_ + k2];
        w_s[idx] = v;
    }
    __syncthreads();

    int q  = t & 7;    // oc quad (q==7 idle)
    int pl = t >> 3;   // 0..31
    if (q < 7) {
        float a[8];
        #pragma unroll
        for (int j = 0; j < 8; j++) a[j] = 0.f;
        #pragma unroll
        for (int ki = 0; ki < 3; ki++) {
            #pragma unroll
            for (int kj = 0; kj < 3; kj++) {
                int xp0 = pl + kj - 1;           // -1..32
                int xp1 = pl + 32 + kj - 1;      // 31..64
                int r0 = (xp0 >= 0)  ? (ki*64 + xp0) : 192;
                int r1 = (xp1 < 64)  ? (ki*64 + xp1) : 192;
                const float* xr0 = &x_s[r0*XS_ROW];
                const float* xr1 = &x_s[r1*XS_ROW];
                const float* wr  = &w_s[((ki*3 + kj)*128)*WS_OC + q*4];
                #pragma unroll 4
                for (int c = 0; c < 128; c++) {
                    float4 wv = *(const float4*)(wr + c*WS_OC);
                    float xv0 = xr0[c];
                    float xv1 = xr1[c];
                    a[0] = fmaf(xv0, wv.x, a[0]);
                    a[1] = fmaf(xv0, wv.y, a[1]);
                    a[2] = fmaf(xv0, wv.z, a[2]);
                    a[3] = fmaf(xv0, wv.w, a[3]);
                    a[4] = fmaf(xv1, wv.x, a[4]);
                    a[5] = fmaf(xv1, wv.y, a[5]);
                    a[6] = fmaf(xv1, wv.z, a[6]);
                    a[7] = fmaf(xv1, wv.w, a[7]);
                }
            }
        }
        #pragma unroll
        for (int half = 0; half < 2; half++) {
            int wo = pl + half*32;
            int pix = (b*H_ + row)*W_ + wo;
            #pragma unroll
            for (int j = 0; j < 4; j++) {
                int oc = q*4 + j;
                if (oc >= 27) break;
                float v = a[half*4 + j];
                if (oc < 18) {
                    v += offb[oc];
                } else {
                    v += maskb[oc - 18];
                    v = 1.f / (1.f + expf(-v));
                }
                g_offmask[pix*27 + oc] = v;
            }
        }
    }
}

// ===========================================================================
// Kernel C: main deformable conv via mma.sync bf16 hi/lo 3-pass split.
// Block = 128 pixels (2 rows) x 128 oc, 8 warps (warp tile 64x32).
// 18 K-subchunks of 64 channels. smem rows stride 144 B (ldmatrix-clean).
// ===========================================================================
#define SM_A_HI 0
#define SM_A_LO 18432
#define SM_W_HI 36864
#define SM_W_LO 55296
#define SM_MAIN_TOTAL 73728

__global__ void __launch_bounds__(256, 2) dcn_mma_kernel(float* __restrict__ out) {
    extern __shared__ char smem[];
    uint32_t sb = smem_u32(smem);
    const int t    = threadIdx.x;
    const int lane = t & 31;
    const int wid  = t >> 5;
    const int bi   = blockIdx.x;    // 256 blocks
    const int b    = bi >> 5;
    const int rp   = bi & 31;

    const int warp_m = wid & 1;     // 64-pixel half
    const int warp_n = wid >> 1;    // 32-oc quarter
    const uint32_t a_row = (uint32_t)((warp_m*64 + (lane & 15))*144 + (lane >> 4)*16);
    const uint32_t b_row = (uint32_t)((warp_n*32 + (lane & 7))*144 + ((lane >> 3) & 1)*16);
    const uint32_t aHI = sb + SM_A_HI + a_row;
    const uint32_t aLO = sb + SM_A_LO + a_row;
    const uint32_t bHI = sb + SM_W_HI + b_row;
    const uint32_t bLO = sb + SM_W_LO + b_row;

    float acc[4][4][4];
    #pragma unroll
    for (int i = 0; i < 4; i++)
        #pragma unroll
        for (int j = 0; j < 4; j++)
            #pragma unroll
            for (int k = 0; k < 4; k++) acc[i][j][k] = 0.f;

    // sampling constants: 2 threads per pixel
    const int m     = t >> 1;
    const int chalf = t & 1;
    const int row   = rp*2 + (m >> 6);
    const int col   = m & 63;
    const int pix   = (b*H_ + row)*W_ + col;
    const float4* xb4 = (const float4*)g_xT + (size_t)b * H_ * W_ * (C_/4);

    for (int k2 = 0; k2 < K2_; k2++) {
        // per-pixel sampling geometry (once per k2)
        float offy = g_offmask[pix*27 + 2*k2];
        float offx = g_offmask[pix*27 + 2*k2 + 1];
        float msk  = g_offmask[pix*27 + 18 + k2];
        int ki = k2 / 3, kj = k2 - ki*3;
        float py = (float)(row - 1 + ki) + offy;
        float px = (float)(col - 1 + kj) + offx;
        float y0f = floorf(py), x0f = floorf(px);
        float ly = py - y0f, lx = px - x0f;
        int y0 = (int)y0f, x0 = (int)x0f;
        float w00 = (1.f-ly)*(1.f-lx)*msk;
        float w01 = (1.f-ly)*lx*msk;
        float w10 = ly*(1.f-lx)*msk;
        float w11 = ly*lx*msk;
        bool vy0 = (y0 >= 0) && (y0 < H_);
        bool vy1 = (y0+1 >= 0) && (y0+1 < H_);
        bool vx0 = (x0 >= 0) && (x0 < W_);
        bool vx1 = (x0+1 >= 0) && (x0+1 < W_);
        bool p00 = vy0 && vx0, p01 = vy0 && vx1;
        bool p10 = vy1 && vx0, p11 = vy1 && vx1;
        int i00 = (y0*W_ + x0)*32;
        int i01 = i00 + 32;
        int i10 = i00 + W_*32;
        int i11 = i10 + 32;
        float4 zero = make_float4(0.f, 0.f, 0.f, 0.f);

        #pragma unroll
        for (int ch = 0; ch < 2; ch++) {
            __syncthreads();   // previous subchunk's mma reads finished

            // ---- stage W subchunk: [oc][c_local 0..31] hi/lo ----
            #pragma unroll
            for (int it = 0; it < 16; it++) {
                int idx = it*256 + t;            // 0..4095
                int oc = idx >> 5;
                int jl = idx & 31;
                int gidx = k2*8192 + oc*64 + ch*32 + jl;
                uint32_t so = (uint32_t)(oc*144 + jl*4);
                *(uint32_t*)(smem + SM_W_HI + so) = g_whi[gidx];
                *(uint32_t*)(smem + SM_W_LO + so) = g_wlo[gidx];
            }

            // ---- sample A subchunk: 64 channels, 8 quads per thread ----
            #pragma unroll
            for (int i = 0; i < 8; i++) {
                int q_local = i*2 + chalf;       // 0..15
                int qg = ch*16 + q_local;        // global channel quad
                float4 v00 = p00 ? xb4[i00 + qg] : zero;
                float4 v01 = p01 ? xb4[i01 + qg] : zero;
                float4 v10 = p10 ? xb4[i10 + qg] : zero;
                float4 v11 = p11 ? xb4[i11 + qg] : zero;
                float r0 = w00*v00.x + w01*v01.x + w10*v10.x + w11*v11.x;
                float r1 = w00*v00.y + w01*v01.y + w10*v10.y + w11*v11.y;
                float r2 = w00*v00.z + w01*v01.z + w10*v10.z + w11*v11.z;
                float r3 = w00*v00.w + w01*v01.w + w10*v10.w + w11*v11.w;
                __nv_bfloat16 h0 = __float2bfloat16(r0);
                __nv_bfloat16 h1 = __float2bfloat16(r1);
                __nv_bfloat16 h2 = __float2bfloat16(r2);
                __nv_bfloat16 h3 = __float2bfloat16(r3);
                __nv_bfloat16 l0 = __float2bfloat16(r0 - __bfloat162float(h0));
                __nv_bfloat16 l1 = __float2bfloat16(r1 - __bfloat162float(h1));
                __nv_bfloat16 l2 = __float2bfloat16(r2 - __bfloat162float(h2));
                __nv_bfloat16 l3 = __float2bfloat16(r3 - __bfloat162float(h3));
                uint32_t so = (uint32_t)(m*144 + q_local*8);
                *(uint2*)(smem + SM_A_HI + so) = make_uint2(packbf(h0,h1), packbf(h2,h3));
                *(uint2*)(smem + SM_A_LO + so) = make_uint2(packbf(l0,l1), packbf(l2,l3));
            }

            __syncthreads();

            // ---- mma: 3 passes (hh, hi*lo, lo*hi) x 4 k-steps x 16 tiles ----
            #pragma unroll
            for (int pass = 0; pass < 3; pass++) {
                uint32_t ab = (pass == 2) ? aLO : aHI;
                uint32_t bb = (pass == 1) ? bLO : bHI;
                #pragma unroll
                for (int ks = 0; ks < 4; ks++) {
                    uint32_t afr[4][4];
                    uint32_t bfr[4][2];
                    #pragma unroll
                    for (int mt = 0; mt < 4; mt++)
                        ldsm4(afr[mt], ab + mt*2304 + ks*32);
                    #pragma unroll
                    for (int nt = 0; nt < 4; nt++)
                        ldsm2(bfr[nt], bb + nt*1152 + ks*32);
                    #pragma unroll
                    for (int mt = 0; mt < 4; mt++)
                        #pragma unroll
                        for (int nt = 0; nt < 4; nt++)
                            mma16816(acc[mt][nt], afr[mt], bfr[nt]);
                }
            }
        }
    }

    // ---- epilogue: transpose acc through smem, coalesced NCHW stores ----
    __syncthreads();
    float* O_s = (float*)smem;     // [oc][pix], stride 132
    const int g   = lane >> 2;
    const int tig = lane & 3;
    #pragma unroll
    for (int mt = 0; mt < 4; mt++) {
        #pragma unroll
        for (int nt = 0; nt < 4; nt++) {
            int p0 = warp_m*64 + mt*16 + g;
            int o0 = warp_n*32 + nt*8 + tig*2;
            O_s[(o0  )*132 + p0    ] = acc[mt][nt][0];
            O_s[(o0+1)*132 + p0    ] = acc[mt][nt][1];
            O_s[(o0  )*132 + p0 + 8] = acc[mt][nt][2];
            O_s[(o0+1)*132 + p0 + 8] = acc[mt][nt][3];
        }
    }
    __syncthreads();
    // 128 oc x 128 pix = 16384 elements / 256 threads = 64 iterations
    #pragma unroll 4
    for (int it = 0; it < 64; it++) {
        int idx = it*256 + t;
        int oc = idx >> 7;
        int p  = idx & 127;
        out[(((size_t)b*O_ + oc)*H_ + rp*2 + (p >> 6))*W_ + (p & 63)] =
            O_s[oc*132 + p];
    }
}

// ===========================================================================
extern "C" void kernel_launch(void* const* d_in, const int* in_sizes, int n_in,
                              void* d_out, int out_size) {
    const float* x      = (const float*)d_in[0];
    const float* weight = (const float*)d_in[1];
    const float* offw   = (const float*)d_in[2];
    const float* offb   = (const float*)d_in[3];
    const float* maskw  = (const float*)d_in[4];
    const float* maskb  = (const float*)d_in[5];
    float* out = (float*)d_out;

    static bool attr_set = false;
    if (!attr_set) {
        cudaFuncSetAttribute(offmask_kernel,
            cudaFuncAttributeMaxDynamicSharedMemorySize,
            SMEM_B_FLOATS * (int)sizeof(float));
        cudaFuncSetAttribute(dcn_mma_kernel,
            cudaFuncAttributeMaxDynamicSharedMemorySize, SM_MAIN_TOTAL);
        attr_set = true;
    }

    transpose_kernel<<<(B_*H_*W_*C_)/256, 256>>>(x);
    wsplit_kernel<<<(K2_*O_*C_/2 + 255)/256, 256>>>(weight);
    offmask_kernel<<<B_*H_, 256, SMEM_B_FLOATS*sizeof(float)>>>(
        offw, offb, maskw, maskb);
    dcn_mma_kernel<<<256, 256, SM_MAIN_TOTAL>>>(out);
}

// round 7
// speedup vs baseline: 1.6990x; 1.0628x over previous
#include <cuda_runtime.h>
#include <cuda_bf16.h>
#include <math.h>
#include <stdint.h>

// Problem constants
#define B_  8
#define C_  128
#define H_  64
#define W_  64
#define O_  128
#define K2_ 9
#define E_  1152   // C_*K2_

// Scratch (device globals; no allocation allowed)
__device__ float    g_xT [B_*H_*W_*C_];      // NHWC fp32, 16.8 MB
__device__ uint32_t g_xhi[B_*H_*W_*C_/2];    // NHWC bf16x2 hi split
__device__ uint32_t g_xlo[B_*H_*W_*C_/2];    // NHWC bf16x2 lo split
__device__ float    g_offmask[B_*H_*W_*27];  // 18 offsets + 9 sigmoided masks / pixel
__device__ uint32_t g_whi[K2_*O_*C_/2];      // main weight hi, [k2][oc][c/2]
__device__ uint32_t g_wlo[K2_*O_*C_/2];      // main weight lo
__device__ uint32_t g_owhi[K2_*32*C_/2];     // offset/mask weight hi, [k2][oc32][c/2]
__device__ uint32_t g_owlo[K2_*32*C_/2];     // offset/mask weight lo

// ===========================================================================
// Helpers (baseline PTX only: ldmatrix + mma.sync)
// ===========================================================================
__device__ __forceinline__ uint32_t smem_u32(const void* p) {
    uint32_t a;
    asm("{ .reg .u64 t; cvta.to.shared.u64 t, %1; cvt.u32.u64 %0, t; }"
        : "=r"(a) : "l"(p));
    return a;
}
__device__ __forceinline__ void ldsm4(uint32_t* r, uint32_t addr) {
    asm volatile("ldmatrix.sync.aligned.m8n8.x4.shared.b16 {%0,%1,%2,%3}, [%4];"
        : "=r"(r[0]), "=r"(r[1]), "=r"(r[2]), "=r"(r[3]) : "r"(addr));
}
__device__ __forceinline__ void ldsm2(uint32_t* r, uint32_t addr) {
    asm volatile("ldmatrix.sync.aligned.m8n8.x2.shared.b16 {%0,%1}, [%2];"
        : "=r"(r[0]), "=r"(r[1]) : "r"(addr));
}
__device__ __forceinline__ void mma16816(float* c, const uint32_t* a, const uint32_t* b) {
    asm volatile(
        "mma.sync.aligned.m16n8k16.row.col.f32.bf16.bf16.f32 "
        "{%0,%1,%2,%3}, {%4,%5,%6,%7}, {%8,%9}, {%0,%1,%2,%3};"
        : "+f"(c[0]), "+f"(c[1]), "+f"(c[2]), "+f"(c[3])
        : "r"(a[0]), "r"(a[1]), "r"(a[2]), "r"(a[3]), "r"(b[0]), "r"(b[1]));
}
__device__ __forceinline__ uint32_t packbf(__nv_bfloat16 a, __nv_bfloat16 b) {
    __nv_bfloat162 t(a, b);
    return *(uint32_t*)&t;
}
__device__ __forceinline__ void split2(float v0, float v1, uint32_t& hi, uint32_t& lo) {
    __nv_bfloat16 h0 = __float2bfloat16(v0);
    __nv_bfloat16 h1 = __float2bfloat16(v1);
    __nv_bfloat16 l0 = __float2bfloat16(v0 - __bfloat162float(h0));
    __nv_bfloat16 l1 = __float2bfloat16(v1 - __bfloat162float(h1));
    hi = packbf(h0, h1);
    lo = packbf(l0, l1);
}

// ===========================================================================
// Kernel A: NCHW -> NHWC transpose + bf16 hi/lo split of x
// ===========================================================================
__global__ void transpose_kernel(const float* __restrict__ x) {
    int i2 = blockIdx.x * blockDim.x + threadIdx.x;   // channel pairs
    if (i2 >= B_*H_*W_*C_/2) return;
    int cp = i2 & 63;
    int t  = i2 >> 6;
    int xw = t & 63; t >>= 6;
    int y  = t & 63; t >>= 6;
    int b  = t;
    int c = cp * 2;
    float v0 = x[((b*C_ + c  )*H_ + y)*W_ + xw];
    float v1 = x[((b*C_ + c+1)*H_ + y)*W_ + xw];
    ((float2*)g_xT)[i2] = make_float2(v0, v1);
    uint32_t hi, lo;
    split2(v0, v1, hi, lo);
    g_xhi[i2] = hi;
    g_xlo[i2] = lo;
}

// ===========================================================================
// Kernel A2: main weight hi/lo split into [k2][oc][c] bf16x2
// ===========================================================================
__global__ void wsplit_kernel(const float* __restrict__ w) {
    int i2 = blockIdx.x * blockDim.x + threadIdx.x;
    if (i2 >= K2_*O_*C_/2) return;
    int cpair = i2 & 63;
    int oc    = (i2 >> 6) & 127;
    int k2    = i2 >> 13;
    int c = cpair * 2;
    uint32_t hi, lo;
    split2(w[oc*E_ + c*K2_ + k2], w[oc*E_ + (c+1)*K2_ + k2], hi, lo);
    g_whi[i2] = hi;
    g_wlo[i2] = lo;
}

// ===========================================================================
// Kernel A3: offset/mask weight pack: oc 0..17 = offw, 18..26 = maskw, 27..31 = 0
// ===========================================================================
__global__ void owpack_kernel(const float* __restrict__ offw,
                              const float* __restrict__ maskw) {
    int i2 = blockIdx.x * blockDim.x + threadIdx.x;
    if (i2 >= K2_*32*C_/2) return;
    int cp  = i2 & 63;
    int oc  = (i2 >> 6) & 31;
    int k2  = i2 >> 11;
    int c = cp * 2;
    float v0 = 0.f, v1 = 0.f;
    if (oc < 18) {
        v0 = offw[oc*E_ + c*K2_ + k2];
        v1 = offw[oc*E_ + (c+1)*K2_ + k2];
    } else if (oc < 27) {
        v0 = maskw[(oc-18)*E_ + c*K2_ + k2];
        v1 = maskw[(oc-18)*E_ + (c+1)*K2_ + k2];
    }
    uint32_t hi, lo;
    split2(v0, v1, hi, lo);
    g_owhi[i2] = hi;
    g_owlo[i2] = lo;
}

// ===========================================================================
// Kernel B: offset+mask conv via HMMA. Block = 128 pixels (2 rows) x 32 oc.
// A = im2col of x (hi/lo bf16), 9 k2 chunks of K=128. Row stride 272 B.
// ===========================================================================
#define OM_A_HI 0
#define OM_A_LO 34816
#define OM_B_HI 69632
#define OM_B_LO 78336
#define OM_BIAS 87040
#define OM_TOTAL 87296

__global__ void __launch_bounds__(256, 2) offmask_mma_kernel(
    const float* __restrict__ offb, const float* __restrict__ maskb) {
    extern __shared__ char smem[];
    uint32_t sb = smem_u32(smem);
    const int t    = threadIdx.x;
    const int lane = t & 31;
    const int wid  = t >> 5;
    const int bi   = blockIdx.x;     // 256
    const int b    = bi >> 5;
    const int rp   = bi & 31;

    float* bias_s = (float*)(smem + OM_BIAS);
    if (t < 32)
        bias_s[t] = (t < 18) ? offb[t] : (t < 27 ? maskb[t-18] : 0.f);

    const uint32_t aOff = (uint32_t)((wid*16 + (lane & 15))*272 + (lane >> 4)*16);
    const uint32_t bOff = (uint32_t)((lane & 7)*272 + ((lane >> 3) & 1)*16);

    float acc[4][4];
    #pragma unroll
    for (int i = 0; i < 4; i++)
        #pragma unroll
        for (int j = 0; j < 4; j++) acc[i][j] = 0.f;

    // A staging: 2 threads per pixel
    const int m    = t >> 1;
    const int half = t & 1;
    const int row  = rp*2 + (m >> 6);
    const int col  = m & 63;
    const uint4* xh4 = (const uint4*)g_xhi;
    const uint4* xl4 = (const uint4*)g_xlo;

    for (int k2 = 0; k2 < K2_; k2++) {
        __syncthreads();
        // ---- B chunk: 32 oc x 64 cpairs ----
        #pragma unroll
        for (int it = 0; it < 8; it++) {
            int idx = it*256 + t;            // 0..2047
            int oc = idx >> 6;
            int cp = idx & 63;
            uint32_t so = (uint32_t)(oc*272 + cp*4);
            *(uint32_t*)(smem + OM_B_HI + so) = g_owhi[k2*2048 + idx];
            *(uint32_t*)(smem + OM_B_LO + so) = g_owlo[k2*2048 + idx];
        }
        // ---- A chunk: im2col (zero-padded) ----
        {
            int ki = k2 / 3, kj = k2 - ki*3;
            int sy = row - 1 + ki;
            int sx = col - 1 + kj;
            bool valid = (sy >= 0) && (sy < H_) && (sx >= 0) && (sx < W_);
            uint32_t abase = (uint32_t)(m*272 + half*128);
            if (valid) {
                int gb = (((b*H_ + sy)*W_ + sx)*64 + half*32) >> 2;  // uint4 index
                #pragma unroll
                for (int j4 = 0; j4 < 8; j4++) {
                    *(uint4*)(smem + OM_A_HI + abase + j4*16) = xh4[gb + j4];
                    *(uint4*)(smem + OM_A_LO + abase + j4*16) = xl4[gb + j4];
                }
            } else {
                uint4 z = make_uint4(0,0,0,0);
                #pragma unroll
                for (int j4 = 0; j4 < 8; j4++) {
                    *(uint4*)(smem + OM_A_HI + abase + j4*16) = z;
                    *(uint4*)(smem + OM_A_LO + abase + j4*16) = z;
                }
            }
        }
        __syncthreads();

        // ---- MMA: 3 passes x 8 ksteps x 4 n-tiles ----
        #pragma unroll
        for (int pass = 0; pass < 3; pass++) {
            uint32_t ab = sb + ((pass == 2) ? OM_A_LO : OM_A_HI) + aOff;
            uint32_t bb = sb + ((pass == 1) ? OM_B_LO : OM_B_HI) + bOff;
            #pragma unroll
            for (int ks = 0; ks < 8; ks++) {
                uint32_t afr[4];
                ldsm4(afr, ab + ks*32);
                #pragma unroll
                for (int nt = 0; nt < 4; nt++) {
                    uint32_t bfr[2];
                    ldsm2(bfr, bb + nt*2176 + ks*32);
                    mma16816(acc[nt], afr, bfr);
                }
            }
        }
    }

    // ---- epilogue: bias + sigmoid, scatter to g_offmask ----
    const int r0  = lane >> 2;
    const int cl0 = (lane & 3)*2;
    #pragma unroll
    for (int nt = 0; nt < 4; nt++) {
        #pragma unroll
        for (int j = 0; j < 4; j++) {
            int oc = nt*8 + cl0 + (j & 1);
            if (oc >= 27) continue;
            int pl  = wid*16 + r0 + (j >> 1)*8;       // pixel in block
            int prow = rp*2 + (pl >> 6);
            int pcol = pl & 63;
            int gpix = (b*H_ + prow)*W_ + pcol;
            float v = acc[nt][j] + bias_s[oc];
            if (oc >= 18) v = 1.f / (1.f + expf(-v));
            g_offmask[gpix*27 + oc] = v;
        }
    }
}

// ===========================================================================
// Kernel C: main deformable conv via mma.sync bf16 hi/lo 3-pass split.
// Block = 64 pixels (1 row) x 128 oc, 8 warps (warp tile 32x32), grid 512.
// 18 K-subchunks of 64 channels. smem rows stride 144 B.
// ===========================================================================
#define SM_A_HI 0
#define SM_A_LO 9216
#define SM_W_HI 18432
#define SM_W_LO 36864
#define SM_MAIN_TOTAL 55296

__global__ void __launch_bounds__(256, 3) dcn_mma_kernel(float* __restrict__ out) {
    extern __shared__ char smem[];
    uint32_t sb = smem_u32(smem);
    const int t    = threadIdx.x;
    const int lane = t & 31;
    const int wid  = t >> 5;
    const int bi   = blockIdx.x;    // 512 blocks
    const int b    = bi >> 6;
    const int row  = bi & 63;

    const int warp_m = wid & 1;     // 32-pixel half
    const int warp_n = wid >> 1;    // 32-oc quarter
    const uint32_t a_off = (uint32_t)((warp_m*32 + (lane & 15))*144 + (lane >> 4)*16);
    const uint32_t b_off = (uint32_t)((warp_n*32 + (lane & 7))*144 + ((lane >> 3) & 1)*16);
    const uint32_t aHI = sb + SM_A_HI + a_off;
    const uint32_t aLO = sb + SM_A_LO + a_off;
    const uint32_t bHI = sb + SM_W_HI + b_off;
    const uint32_t bLO = sb + SM_W_LO + b_off;

    float acc[2][4][4];
    #pragma unroll
    for (int i = 0; i < 2; i++)
        #pragma unroll
        for (int j = 0; j < 4; j++)
            #pragma unroll
            for (int k = 0; k < 4; k++) acc[i][j][k] = 0.f;

    // sampling: 4 threads per pixel
    const int m  = t >> 2;          // pixel 0..63
    const int cq = t & 3;           // channel-quad group
    const int col = m;
    const int pix = (b*H_ + row)*W_ + col;
    const float4* xb4 = (const float4*)g_xT + (size_t)b * H_ * W_ * (C_/4);

    for (int k2 = 0; k2 < K2_; k2++) {
        float offy = g_offmask[pix*27 + 2*k2];
        float offx = g_offmask[pix*27 + 2*k2 + 1];
        float msk  = g_offmask[pix*27 + 18 + k2];
        int ki = k2 / 3, kj = k2 - ki*3;
        float py = (float)(row - 1 + ki) + offy;
        float px = (float)(col - 1 + kj) + offx;
        float y0f = floorf(py), x0f = floorf(px);
        float ly = py - y0f, lx = px - x0f;
        int y0 = (int)y0f, x0 = (int)x0f;
        float w00 = (1.f-ly)*(1.f-lx)*msk;
        float w01 = (1.f-ly)*lx*msk;
        float w10 = ly*(1.f-lx)*msk;
        float w11 = ly*lx*msk;
        bool vy0 = (y0 >= 0) && (y0 < H_);
        bool vy1 = (y0+1 >= 0) && (y0+1 < H_);
        bool vx0 = (x0 >= 0) && (x0 < W_);
        bool vx1 = (x0+1 >= 0) && (x0+1 < W_);
        bool p00 = vy0 && vx0, p01 = vy0 && vx1;
        bool p10 = vy1 && vx0, p11 = vy1 && vx1;
        int i00 = (y0*W_ + x0)*32;
        int i01 = i00 + 32;
        int i10 = i00 + W_*32;
        int i11 = i10 + 32;
        float4 zero = make_float4(0.f, 0.f, 0.f, 0.f);

        #pragma unroll
        for (int ch = 0; ch < 2; ch++) {
            __syncthreads();

            // ---- stage W subchunk ----
            #pragma unroll
            for (int it = 0; it < 16; it++) {
                int idx = it*256 + t;            // 0..4095
                int oc = idx >> 5;
                int jl = idx & 31;
                int gidx = k2*8192 + oc*64 + ch*32 + jl;
                uint32_t so = (uint32_t)(oc*144 + jl*4);
                *(uint32_t*)(smem + SM_W_HI + so) = g_whi[gidx];
                *(uint32_t*)(smem + SM_W_LO + so) = g_wlo[gidx];
            }

            // ---- sample A subchunk: 4 quads per thread ----
            #pragma unroll
            for (int i = 0; i < 4; i++) {
                int q_local = i*4 + cq;          // 0..15
                int qg = ch*16 + q_local;
                float4 v00 = p00 ? xb4[i00 + qg] : zero;
                float4 v01 = p01 ? xb4[i01 + qg] : zero;
                float4 v10 = p10 ? xb4[i10 + qg] : zero;
                float4 v11 = p11 ? xb4[i11 + qg] : zero;
                float r0 = w00*v00.x + w01*v01.x + w10*v10.x + w11*v11.x;
                float r1 = w00*v00.y + w01*v01.y + w10*v10.y + w11*v11.y;
                float r2 = w00*v00.z + w01*v01.z + w10*v10.z + w11*v11.z;
                float r3 = w00*v00.w + w01*v01.w + w10*v10.w + w11*v11.w;
                uint32_t hi01, lo01, hi23, lo23;
                split2(r0, r1, hi01, lo01);
                split2(r2, r3, hi23, lo23);
                uint32_t so = (uint32_t)(m*144 + q_local*8);
                *(uint2*)(smem + SM_A_HI + so) = make_uint2(hi01, hi23);
                *(uint2*)(smem + SM_A_LO + so) = make_uint2(lo01, lo23);
            }

            __syncthreads();

            // ---- mma: 3 passes x 4 ksteps x (2 m-tiles x 4 n-tiles) ----
            #pragma unroll
            for (int pass = 0; pass < 3; pass++) {
                uint32_t ab = (pass == 2) ? aLO : aHI;
                uint32_t bb = (pass == 1) ? bLO : bHI;
                #pragma unroll
                for (int ks = 0; ks < 4; ks++) {
                    uint32_t afr[2][4];
                    uint32_t bfr[4][2];
                    #pragma unroll
                    for (int mt = 0; mt < 2; mt++)
                        ldsm4(afr[mt], ab + mt*2304 + ks*32);
                    #pragma unroll
                    for (int nt = 0; nt < 4; nt++)
                        ldsm2(bfr[nt], bb + nt*1152 + ks*32);
                    #pragma unroll
                    for (int mt = 0; mt < 2; mt++)
                        #pragma unroll
                        for (int nt = 0; nt < 4; nt++)
                            mma16816(acc[mt][nt], afr[mt], bfr[nt]);
                }
            }
        }
    }

    // ---- epilogue: transpose through smem, coalesced NCHW stores ----
    __syncthreads();
    float* O_s = (float*)smem;     // [oc][pix 64], stride 68
    const int g   = lane >> 2;
    const int tig = lane & 3;
    #pragma unroll
    for (int mt = 0; mt < 2; mt++) {
        #pragma unroll
        for (int nt = 0; nt < 4; nt++) {
            int p0 = warp_m*32 + mt*16 + g;
            int o0 = warp_n*32 + nt*8 + tig*2;
            O_s[(o0  )*68 + p0    ] = acc[mt][nt][0];
            O_s[(o0+1)*68 + p0    ] = acc[mt][nt][1];
            O_s[(o0  )*68 + p0 + 8] = acc[mt][nt][2];
            O_s[(o0+1)*68 + p0 + 8] = acc[mt][nt][3];
        }
    }
    __syncthreads();
    // 128 oc x 64 pix = 8192 / 256 = 32 iterations
    #pragma unroll 4
    for (int it = 0; it < 32; it++) {
        int idx = it*256 + t;
        int oc = idx >> 6;
        int p  = idx & 63;
        out[(((size_t)b*O_ + oc)*H_ + row)*W_ + p] = O_s[oc*68 + p];
    }
}

// ===========================================================================
extern "C" void kernel_launch(void* const* d_in, const int* in_sizes, int n_in,
                              void* d_out, int out_size) {
    const float* x      = (const float*)d_in[0];
    const float* weight = (const float*)d_in[1];
    const float* offw   = (const float*)d_in[2];
    const float* offb   = (const float*)d_in[3];
    const float* maskw  = (const float*)d_in[4];
    const float* maskb  = (const float*)d_in[5];
    float* out = (float*)d_out;

    static bool attr_set = false;
    if (!attr_set) {
        cudaFuncSetAttribute(offmask_mma_kernel,
            cudaFuncAttributeMaxDynamicSharedMemorySize, OM_TOTAL);
        cudaFuncSetAttribute(dcn_mma_kernel,
            cudaFuncAttributeMaxDynamicSharedMemorySize, SM_MAIN_TOTAL);
        attr_set = true;
    }

    transpose_kernel<<<(B_*H_*W_*C_/2 + 255)/256, 256>>>(x);
    wsplit_kernel<<<(K2_*O_*C_/2 + 255)/256, 256>>>(weight);
    owpack_kernel<<<(K2_*32*C_/2 + 255)/256, 256>>>(offw, maskw);
    offmask_mma_kernel<<<256, 256, OM_TOTAL>>>(offb, maskb);
    dcn_mma_kernel<<<512, 256, SM_MAIN_TOTAL>>>(out);
}

// round 8
// speedup vs baseline: 3.3413x; 1.9667x over previous
#include <cuda_runtime.h>
#include <cuda_bf16.h>
#include <math.h>
#include <stdint.h>

// Problem constants
#define B_  8
#define C_  128
#define H_  64
#define W_  64
#define O_  128
#define K2_ 9
#define E_  1152   // C_*K2_
#define NPIX (B_*H_*W_)      // 32768
#define PITCH 576            // u32 per pixel row of cols (1152 bf16 / 2)

// Scratch (device globals; no allocation allowed)
__device__ float    g_xT [B_*H_*W_*C_];      // NHWC fp32
__device__ uint32_t g_xhi[B_*H_*W_*C_/2];    // NHWC bf16x2 hi split
__device__ uint32_t g_xlo[B_*H_*W_*C_/2];    // NHWC bf16x2 lo split
__device__ float    g_offmask[NPIX*27];      // 18 offsets + 9 sigmoided masks / pixel
__device__ uint32_t g_whi[K2_*O_*C_/2];      // main weight hi, [k2][oc][c/2]
__device__ uint32_t g_wlo[K2_*O_*C_/2];      // main weight lo
__device__ uint32_t g_owhi[K2_*32*C_/2];     // offset/mask weight hi
__device__ uint32_t g_owlo[K2_*32*C_/2];     // offset/mask weight lo
__device__ uint32_t g_colhi[NPIX*PITCH];     // sampled cols hi, [pix][k2][c/2], 75.5MB
__device__ uint32_t g_collo[NPIX*PITCH];     // sampled cols lo

// ===========================================================================
// Helpers (baseline PTX only: ldmatrix + mma.sync)
// ===========================================================================
__device__ __forceinline__ uint32_t smem_u32(const void* p) {
    uint32_t a;
    asm("{ .reg .u64 t; cvta.to.shared.u64 t, %1; cvt.u32.u64 %0, t; }"
        : "=r"(a) : "l"(p));
    return a;
}
__device__ __forceinline__ void ldsm4(uint32_t* r, uint32_t addr) {
    asm volatile("ldmatrix.sync.aligned.m8n8.x4.shared.b16 {%0,%1,%2,%3}, [%4];"
        : "=r"(r[0]), "=r"(r[1]), "=r"(r[2]), "=r"(r[3]) : "r"(addr));
}
__device__ __forceinline__ void ldsm2(uint32_t* r, uint32_t addr) {
    asm volatile("ldmatrix.sync.aligned.m8n8.x2.shared.b16 {%0,%1}, [%2];"
        : "=r"(r[0]), "=r"(r[1]) : "r"(addr));
}
__device__ __forceinline__ void mma16816(float* c, const uint32_t* a, const uint32_t* b) {
    asm volatile(
        "mma.sync.aligned.m16n8k16.row.col.f32.bf16.bf16.f32 "
        "{%0,%1,%2,%3}, {%4,%5,%6,%7}, {%8,%9}, {%0,%1,%2,%3};"
        : "+f"(c[0]), "+f"(c[1]), "+f"(c[2]), "+f"(c[3])
        : "r"(a[0]), "r"(a[1]), "r"(a[2]), "r"(a[3]), "r"(b[0]), "r"(b[1]));
}
__device__ __forceinline__ uint32_t packbf(__nv_bfloat16 a, __nv_bfloat16 b) {
    __nv_bfloat162 t(a, b);
    return *(uint32_t*)&t;
}
__device__ __forceinline__ void split2(float v0, float v1, uint32_t& hi, uint32_t& lo) {
    __nv_bfloat16 h0 = __float2bfloat16(v0);
    __nv_bfloat16 h1 = __float2bfloat16(v1);
    __nv_bfloat16 l0 = __float2bfloat16(v0 - __bfloat162float(h0));
    __nv_bfloat16 l1 = __float2bfloat16(v1 - __bfloat162float(h1));
    hi = packbf(h0, h1);
    lo = packbf(l0, l1);
}

// ===========================================================================
// Kernel A: NCHW -> NHWC transpose + bf16 hi/lo split of x
// ===========================================================================
__global__ void transpose_kernel(const float* __restrict__ x) {
    int i2 = blockIdx.x * blockDim.x + threadIdx.x;   // channel pairs
    if (i2 >= B_*H_*W_*C_/2) return;
    int cp = i2 & 63;
    int t  = i2 >> 6;
    int xw = t & 63; t >>= 6;
    int y  = t & 63; t >>= 6;
    int b  = t;
    int c = cp * 2;
    float v0 = x[((b*C_ + c  )*H_ + y)*W_ + xw];
    float v1 = x[((b*C_ + c+1)*H_ + y)*W_ + xw];
    ((float2*)g_xT)[i2] = make_float2(v0, v1);
    uint32_t hi, lo;
    split2(v0, v1, hi, lo);
    g_xhi[i2] = hi;
    g_xlo[i2] = lo;
}

// ===========================================================================
// Kernel A2: main weight hi/lo split into [k2][oc][c] bf16x2
// ===========================================================================
__global__ void wsplit_kernel(const float* __restrict__ w) {
    int i2 = blockIdx.x * blockDim.x + threadIdx.x;
    if (i2 >= K2_*O_*C_/2) return;
    int cpair = i2 & 63;
    int oc    = (i2 >> 6) & 127;
    int k2    = i2 >> 13;
    int c = cpair * 2;
    uint32_t hi, lo;
    split2(w[oc*E_ + c*K2_ + k2], w[oc*E_ + (c+1)*K2_ + k2], hi, lo);
    g_whi[i2] = hi;
    g_wlo[i2] = lo;
}

// ===========================================================================
// Kernel A3: offset/mask weight pack: oc 0..17 = offw, 18..26 = maskw, rest 0
// ===========================================================================
__global__ void owpack_kernel(const float* __restrict__ offw,
                              const float* __restrict__ maskw) {
    int i2 = blockIdx.x * blockDim.x + threadIdx.x;
    if (i2 >= K2_*32*C_/2) return;
    int cp  = i2 & 63;
    int oc  = (i2 >> 6) & 31;
    int k2  = i2 >> 11;
    int c = cp * 2;
    float v0 = 0.f, v1 = 0.f;
    if (oc < 18) {
        v0 = offw[oc*E_ + c*K2_ + k2];
        v1 = offw[oc*E_ + (c+1)*K2_ + k2];
    } else if (oc < 27) {
        v0 = maskw[(oc-18)*E_ + c*K2_ + k2];
        v1 = maskw[(oc-18)*E_ + (c+1)*K2_ + k2];
    }
    uint32_t hi, lo;
    split2(v0, v1, hi, lo);
    g_owhi[i2] = hi;
    g_owlo[i2] = lo;
}

// ===========================================================================
// Kernel B: offset+mask conv via HMMA. Block = 128 pixels (2 rows) x 32 oc.
// (unchanged from R7 — measured 79us)
// ===========================================================================
#define OM_A_HI 0
#define OM_A_LO 34816
#define OM_B_HI 69632
#define OM_B_LO 78336
#define OM_BIAS 87040
#define OM_TOTAL 87296

__global__ void __launch_bounds__(256, 2) offmask_mma_kernel(
    const float* __restrict__ offb, const float* __restrict__ maskb) {
    extern __shared__ char smem[];
    uint32_t sb = smem_u32(smem);
    const int t    = threadIdx.x;
    const int lane = t & 31;
    const int wid  = t >> 5;
    const int bi   = blockIdx.x;     // 256
    const int b    = bi >> 5;
    const int rp   = bi & 31;

    float* bias_s = (float*)(smem + OM_BIAS);
    if (t < 32)
        bias_s[t] = (t < 18) ? offb[t] : (t < 27 ? maskb[t-18] : 0.f);

    const uint32_t aOff = (uint32_t)((wid*16 + (lane & 15))*272 + (lane >> 4)*16);
    const uint32_t bOff = (uint32_t)((lane & 7)*272 + ((lane >> 3) & 1)*16);

    float acc[4][4];
    #pragma unroll
    for (int i = 0; i < 4; i++)
        #pragma unroll
        for (int j = 0; j < 4; j++) acc[i][j] = 0.f;

    const int m    = t >> 1;
    const int half = t & 1;
    const int row  = rp*2 + (m >> 6);
    const int col  = m & 63;
    const uint4* xh4 = (const uint4*)g_xhi;
    const uint4* xl4 = (const uint4*)g_xlo;

    for (int k2 = 0; k2 < K2_; k2++) {
        __syncthreads();
        #pragma unroll
        for (int it = 0; it < 8; it++) {
            int idx = it*256 + t;
            int oc = idx >> 6;
            int cp = idx & 63;
            uint32_t so = (uint32_t)(oc*272 + cp*4);
            *(uint32_t*)(smem + OM_B_HI + so) = g_owhi[k2*2048 + idx];
            *(uint32_t*)(smem + OM_B_LO + so) = g_owlo[k2*2048 + idx];
        }
        {
            int ki = k2 / 3, kj = k2 - ki*3;
            int sy = row - 1 + ki;
            int sx = col - 1 + kj;
            bool valid = (sy >= 0) && (sy < H_) && (sx >= 0) && (sx < W_);
            uint32_t abase = (uint32_t)(m*272 + half*128);
            if (valid) {
                int gb = (((b*H_ + sy)*W_ + sx)*64 + half*32) >> 2;
                #pragma unroll
                for (int j4 = 0; j4 < 8; j4++) {
                    *(uint4*)(smem + OM_A_HI + abase + j4*16) = xh4[gb + j4];
                    *(uint4*)(smem + OM_A_LO + abase + j4*16) = xl4[gb + j4];
                }
            } else {
                uint4 z = make_uint4(0,0,0,0);
                #pragma unroll
                for (int j4 = 0; j4 < 8; j4++) {
                    *(uint4*)(smem + OM_A_HI + abase + j4*16) = z;
                    *(uint4*)(smem + OM_A_LO + abase + j4*16) = z;
                }
            }
        }
        __syncthreads();

        #pragma unroll
        for (int pass = 0; pass < 3; pass++) {
            uint32_t ab = sb + ((pass == 2) ? OM_A_LO : OM_A_HI) + aOff;
            uint32_t bb = sb + ((pass == 1) ? OM_B_LO : OM_B_HI) + bOff;
            #pragma unroll
            for (int ks = 0; ks < 8; ks++) {
                uint32_t afr[4];
                ldsm4(afr, ab + ks*32);
                #pragma unroll
                for (int nt = 0; nt < 4; nt++) {
                    uint32_t bfr[2];
                    ldsm2(bfr, bb + nt*2176 + ks*32);
                    mma16816(acc[nt], afr, bfr);
                }
            }
        }
    }

    const int r0  = lane >> 2;
    const int cl0 = (lane & 3)*2;
    #pragma unroll
    for (int nt = 0; nt < 4; nt++) {
        #pragma unroll
        for (int j = 0; j < 4; j++) {
            int oc = nt*8 + cl0 + (j & 1);
            if (oc >= 27) continue;
            int pl  = wid*16 + r0 + (j >> 1)*8;
            int prow = rp*2 + (pl >> 6);
            int pcol = pl & 63;
            int gpix = (b*H_ + prow)*W_ + pcol;
            float v = acc[nt][j] + bias_s[oc];
            if (oc >= 18) v = 1.f / (1.f + expf(-v));
            g_offmask[gpix*27 + oc] = v;
        }
    }
}

// ===========================================================================
// Kernel S: sample cols to gmem. One warp per (pixel, k2) task.
// Lane = channel quad. Writes bf16x2 hi/lo, [pix][k2][c/2].
// ===========================================================================
__global__ void __launch_bounds__(256) sample_cols_kernel() {
    int task = blockIdx.x * 8 + (threadIdx.x >> 5);   // 294912 tasks
    int lane = threadIdx.x & 31;
    int pix = task / 9;
    int k2  = task - pix*9;
    int b   = pix >> 12;
    int rem = pix & 4095;
    int row = rem >> 6;
    int col = rem & 63;

    float offy = g_offmask[pix*27 + 2*k2];
    float offx = g_offmask[pix*27 + 2*k2 + 1];
    float msk  = g_offmask[pix*27 + 18 + k2];
    int ki = k2 / 3, kj = k2 - ki*3;
    float py = (float)(row - 1 + ki) + offy;
    float px = (float)(col - 1 + kj) + offx;
    float y0f = floorf(py), x0f = floorf(px);
    float ly = py - y0f, lx = px - x0f;
    int y0 = (int)y0f, x0 = (int)x0f;
    float w00 = (1.f-ly)*(1.f-lx)*msk;
    float w01 = (1.f-ly)*lx*msk;
    float w10 = ly*(1.f-lx)*msk;
    float w11 = ly*lx*msk;
    bool vy0 = (y0 >= 0) && (y0 < H_);
    bool vy1 = (y0+1 >= 0) && (y0+1 < H_);
    bool vx0 = (x0 >= 0) && (x0 < W_);
    bool vx1 = (x0+1 >= 0) && (x0+1 < W_);
    bool p00 = vy0 && vx0, p01 = vy0 && vx1;
    bool p10 = vy1 && vx0, p11 = vy1 && vx1;
    const float4* xb4 = (const float4*)g_xT + (size_t)b * H_ * W_ * 32;
    int i00 = (y0*W_ + x0)*32 + lane;
    float4 zero = make_float4(0.f, 0.f, 0.f, 0.f);
    float4 v00 = p00 ? xb4[i00          ] : zero;
    float4 v01 = p01 ? xb4[i00 + 32     ] : zero;
    float4 v10 = p10 ? xb4[i00 + W_*32  ] : zero;
    float4 v11 = p11 ? xb4[i00 + W_*32+32] : zero;
    float r0 = w00*v00.x + w01*v01.x + w10*v10.x + w11*v11.x;
    float r1 = w00*v00.y + w01*v01.y + w10*v10.y + w11*v11.y;
    float r2 = w00*v00.z + w01*v01.z + w10*v10.z + w11*v11.z;
    float r3 = w00*v00.w + w01*v01.w + w10*v10.w + w11*v11.w;
    uint32_t hi01, lo01, hi23, lo23;
    split2(r0, r1, hi01, lo01);
    split2(r2, r3, hi23, lo23);
    int o = pix*PITCH + k2*64 + lane*2;
    *(uint2*)&g_colhi[o] = make_uint2(hi01, hi23);
    *(uint2*)&g_collo[o] = make_uint2(lo01, lo23);
}

// ===========================================================================
// Kernel C: pure GEMM. Block = 128 pix x 128 oc (grid 256), 8 warps 64x32.
// 18 K-subchunks of 64 channels, staging = plain uint4 copies.
// ===========================================================================
#define SM_A_HI 0
#define SM_A_LO 18432
#define SM_W_HI 36864
#define SM_W_LO 55296
#define SM_MAIN_TOTAL 73728

__global__ void __launch_bounds__(256, 2) dcn_gemm_kernel(float* __restrict__ out) {
    extern __shared__ char smem[];
    uint32_t sb = smem_u32(smem);
    const int t    = threadIdx.x;
    const int lane = t & 31;
    const int wid  = t >> 5;
    const int bi   = blockIdx.x;    // 256 blocks, pixels [bi*128, bi*128+128)
    const int b    = bi >> 5;
    const int rp   = bi & 31;

    const int warp_m = wid & 1;
    const int warp_n = wid >> 1;
    const uint32_t a_off = (uint32_t)((warp_m*64 + (lane & 15))*144 + (lane >> 4)*16);
    const uint32_t b_off = (uint32_t)((warp_n*32 + (lane & 7))*144 + ((lane >> 3) & 1)*16);
    const uint32_t aHI = sb + SM_A_HI + a_off;
    const uint32_t aLO = sb + SM_A_LO + a_off;
    const uint32_t bHI = sb + SM_W_HI + b_off;
    const uint32_t bLO = sb + SM_W_LO + b_off;

    float acc[4][4][4];
    #pragma unroll
    for (int i = 0; i < 4; i++)
        #pragma unroll
        for (int j = 0; j < 4; j++)
            #pragma unroll
            for (int k = 0; k < 4; k++) acc[i][j][k] = 0.f;

    // staging mapping: 2 threads per pixel row
    const int sp   = t >> 1;        // pixel 0..127
    const int sh   = t & 1;         // which 16-u32 half
    const int gA   = (bi*128 + sp) * PITCH + sh*16;   // + sub*32

    for (int sub = 0; sub < 18; sub++) {
        __syncthreads();
        // ---- stage A (hi/lo): 4 uint4 each ----
        {
            const uint4* src_h = (const uint4*)&g_colhi[gA + sub*32];
            const uint4* src_l = (const uint4*)&g_collo[gA + sub*32];
            uint32_t so = (uint32_t)(sp*144 + sh*64);
            #pragma unroll
            for (int j = 0; j < 4; j++) {
                *(uint4*)(smem + SM_A_HI + so + j*16) = src_h[j];
                *(uint4*)(smem + SM_A_LO + so + j*16) = src_l[j];
            }
        }
        // ---- stage W (hi/lo): 4 uint4 each ----
        {
            int k2 = sub >> 1;
            int ch = sub & 1;
            #pragma unroll
            for (int it = 0; it < 4; it++) {
                int idx = it*256 + t;           // 0..1023
                int oc = idx >> 3;
                int g  = idx & 7;
                int gi = k2*8192 + oc*64 + ch*32 + g*4;
                uint32_t so = (uint32_t)(oc*144 + g*16);
                *(uint4*)(smem + SM_W_HI + so) = *(const uint4*)&g_whi[gi];
                *(uint4*)(smem + SM_W_LO + so) = *(const uint4*)&g_wlo[gi];
            }
        }
        __syncthreads();

        // ---- mma: 3 passes x 4 ksteps x (4 m x 4 n) ----
        #pragma unroll
        for (int pass = 0; pass < 3; pass++) {
            uint32_t ab = (pass == 2) ? aLO : aHI;
            uint32_t bb = (pass == 1) ? bLO : bHI;
            #pragma unroll
            for (int ks = 0; ks < 4; ks++) {
                uint32_t afr[4][4];
                uint32_t bfr[4][2];
                #pragma unroll
                for (int mt = 0; mt < 4; mt++)
                    ldsm4(afr[mt], ab + mt*2304 + ks*32);
                #pragma unroll
                for (int nt = 0; nt < 4; nt++)
                    ldsm2(bfr[nt], bb + nt*1152 + ks*32);
                #pragma unroll
                for (int mt = 0; mt < 4; mt++)
                    #pragma unroll
                    for (int nt = 0; nt < 4; nt++)
                        mma16816(acc[mt][nt], afr[mt], bfr[nt]);
            }
        }
    }

    // ---- epilogue: transpose through smem, coalesced NCHW stores ----
    __syncthreads();
    float* O_s = (float*)smem;     // [oc][pix], stride 132
    const int g   = lane >> 2;
    const int tig = lane & 3;
    #pragma unroll
    for (int mt = 0; mt < 4; mt++) {
        #pragma unroll
        for (int nt = 0; nt < 4; nt++) {
            int p0 = warp_m*64 + mt*16 + g;
            int o0 = warp_n*32 + nt*8 + tig*2;
            O_s[(o0  )*132 + p0    ] = acc[mt][nt][0];
            O_s[(o0+1)*132 + p0    ] = acc[mt][nt][1];
            O_s[(o0  )*132 + p0 + 8] = acc[mt][nt][2];
            O_s[(o0+1)*132 + p0 + 8] = acc[mt][nt][3];
        }
    }
    __syncthreads();
    // 128 oc x 128 pix = 16384 / 256 = 64 iterations
    #pragma unroll 4
    for (int it = 0; it < 64; it++) {
        int idx = it*256 + t;
        int oc = idx >> 7;
        int p  = idx & 127;
        out[(((size_t)b*O_ + oc)*H_ + rp*2 + (p >> 6))*W_ + (p & 63)] =
            O_s[oc*132 + p];
    }
}

// ===========================================================================
extern "C" void kernel_launch(void* const* d_in, const int* in_sizes, int n_in,
                              void* d_out, int out_size) {
    const float* x      = (const float*)d_in[0];
    const float* weight = (const float*)d_in[1];
    const float* offw   = (const float*)d_in[2];
    const float* offb   = (const float*)d_in[3];
    const float* maskw  = (const float*)d_in[4];
    const float* maskb  = (const float*)d_in[5];
    float* out = (float*)d_out;

    static bool attr_set = false;
    if (!attr_set) {
        cudaFuncSetAttribute(offmask_mma_kernel,
            cudaFuncAttributeMaxDynamicSharedMemorySize, OM_TOTAL);
        cudaFuncSetAttribute(dcn_gemm_kernel,
            cudaFuncAttributeMaxDynamicSharedMemorySize, SM_MAIN_TOTAL);
        attr_set = true;
    }

    transpose_kernel<<<(B_*H_*W_*C_/2 + 255)/256, 256>>>(x);
    wsplit_kernel<<<(K2_*O_*C_/2 + 255)/256, 256>>>(weight);
    owpack_kernel<<<(K2_*32*C_/2 + 255)/256, 256>>>(offw, maskw);
    offmask_mma_kernel<<<256, 256, OM_TOTAL>>>(offb, maskb);
    sample_cols_kernel<<<NPIX*K2_/8, 256>>>();
    dcn_gemm_kernel<<<256, 256, SM_MAIN_TOTAL>>>(out);
}

// round 9
// speedup vs baseline: 4.0451x; 1.2106x over previous
#include <cuda_runtime.h>
#include <cuda_bf16.h>
#include <math.h>
#include <stdint.h>

// Problem constants
#define B_  8
#define C_  128
#define H_  64
#define W_  64
#define O_  128
#define K2_ 9
#define E_  1152   // C_*K2_
#define NPIX (B_*H_*W_)      // 32768
#define PITCH 576            // u32 per pixel row of cols (1152 bf16 / 2)

// Scratch (device globals; no allocation allowed)
__device__ float    g_xT [B_*H_*W_*C_];      // NHWC fp32
__device__ uint32_t g_xhi[B_*H_*W_*C_/2];    // NHWC bf16x2 hi split
__device__ uint32_t g_xlo[B_*H_*W_*C_/2];    // NHWC bf16x2 lo split
__device__ float    g_offmask[NPIX*27];      // 18 offsets + 9 sigmoided masks / pixel
__device__ uint32_t g_whi[K2_*O_*C_/2];      // main weight hi, [k2][oc][c/2]
__device__ uint32_t g_wlo[K2_*O_*C_/2];      // main weight lo
__device__ uint32_t g_owhi[K2_*32*C_/2];     // offset/mask weight hi
__device__ uint32_t g_owlo[K2_*32*C_/2];     // offset/mask weight lo
__device__ uint32_t g_colhi[NPIX*PITCH];     // sampled cols hi, [pix][k2][c/2]
__device__ uint32_t g_collo[NPIX*PITCH];     // sampled cols lo

// ===========================================================================
// Helpers (baseline PTX: ldmatrix + mma.sync + cp.async)
// ===========================================================================
__device__ __forceinline__ uint32_t smem_u32(const void* p) {
    uint32_t a;
    asm("{ .reg .u64 t; cvta.to.shared.u64 t, %1; cvt.u32.u64 %0, t; }"
        : "=r"(a) : "l"(p));
    return a;
}
__device__ __forceinline__ void ldsm4(uint32_t* r, uint32_t addr) {
    asm volatile("ldmatrix.sync.aligned.m8n8.x4.shared.b16 {%0,%1,%2,%3}, [%4];"
        : "=r"(r[0]), "=r"(r[1]), "=r"(r[2]), "=r"(r[3]) : "r"(addr));
}
__device__ __forceinline__ void ldsm2(uint32_t* r, uint32_t addr) {
    asm volatile("ldmatrix.sync.aligned.m8n8.x2.shared.b16 {%0,%1}, [%2];"
        : "=r"(r[0]), "=r"(r[1]) : "r"(addr));
}
__device__ __forceinline__ void mma16816(float* c, const uint32_t* a, const uint32_t* b) {
    asm volatile(
        "mma.sync.aligned.m16n8k16.row.col.f32.bf16.bf16.f32 "
        "{%0,%1,%2,%3}, {%4,%5,%6,%7}, {%8,%9}, {%0,%1,%2,%3};"
        : "+f"(c[0]), "+f"(c[1]), "+f"(c[2]), "+f"(c[3])
        : "r"(a[0]), "r"(a[1]), "r"(a[2]), "r"(a[3]), "r"(b[0]), "r"(b[1]));
}
#define CP_A16(dst, src) \
    asm volatile("cp.async.cg.shared.global [%0], [%1], 16;" \
                 :: "r"(dst), "l"(src))
#define CP_A16Z(dst, src, sz) \
    asm volatile("cp.async.cg.shared.global [%0], [%1], 16, %2;" \
                 :: "r"(dst), "l"(src), "r"(sz))
#define CP_COMMIT() asm volatile("cp.async.commit_group;")
#define CP_WAIT(n)  asm volatile("cp.async.wait_group %0;" :: "n"(n))

__device__ __forceinline__ uint32_t packbf(__nv_bfloat16 a, __nv_bfloat16 b) {
    __nv_bfloat162 t(a, b);
    return *(uint32_t*)&t;
}
__device__ __forceinline__ void split2(float v0, float v1, uint32_t& hi, uint32_t& lo) {
    __nv_bfloat16 h0 = __float2bfloat16(v0);
    __nv_bfloat16 h1 = __float2bfloat16(v1);
    __nv_bfloat16 l0 = __float2bfloat16(v0 - __bfloat162float(h0));
    __nv_bfloat16 l1 = __float2bfloat16(v1 - __bfloat162float(h1));
    hi = packbf(h0, h1);
    lo = packbf(l0, l1);
}

// ===========================================================================
// Kernel A: NCHW -> NHWC transpose + bf16 hi/lo split (smem tile, coalesced)
// Block = (b, y, 32-channel tile); grid B*H*4 = 2048.
// ===========================================================================
__global__ void __launch_bounds__(256) transpose_kernel(const float* __restrict__ x) {
    __shared__ float ts[32][65];
    int bi  = blockIdx.x;
    int ct  = bi & 3;
    int rem = bi >> 2;
    int y   = rem & 63;
    int b   = rem >> 6;
    int c0  = ct * 32;
    int t   = threadIdx.x;

    #pragma unroll
    for (int it = 0; it < 8; it++) {
        int idx = it*256 + t;
        int cl = idx >> 6, xw = idx & 63;
        ts[cl][xw] = x[((b*C_ + c0 + cl)*H_ + y)*W_ + xw];
    }
    __syncthreads();
    #pragma unroll
    for (int it = 0; it < 8; it++) {
        int idx = it*256 + t;
        int cl = idx & 31, xw = idx >> 5;
        g_xT[((b*H_ + y)*W_ + xw)*C_ + c0 + cl] = ts[cl][xw];
    }
    #pragma unroll
    for (int it = 0; it < 4; it++) {
        int idx = it*256 + t;
        int cp = idx & 15, xw = idx >> 4;
        uint32_t hi, lo;
        split2(ts[cp*2][xw], ts[cp*2 + 1][xw], hi, lo);
        int o = ((b*H_ + y)*W_ + xw)*64 + (c0 >> 1) + cp;
        g_xhi[o] = hi;
        g_xlo[o] = lo;
    }
}

// ===========================================================================
// Kernel A2: main weight hi/lo split into [k2][oc][c] bf16x2
// ===========================================================================
__global__ void wsplit_kernel(const float* __restrict__ w) {
    int i2 = blockIdx.x * blockDim.x + threadIdx.x;
    if (i2 >= K2_*O_*C_/2) return;
    int cpair = i2 & 63;
    int oc    = (i2 >> 6) & 127;
    int k2    = i2 >> 13;
    int c = cpair * 2;
    uint32_t hi, lo;
    split2(w[oc*E_ + c*K2_ + k2], w[oc*E_ + (c+1)*K2_ + k2], hi, lo);
    g_whi[i2] = hi;
    g_wlo[i2] = lo;
}

// ===========================================================================
// Kernel A3: offset/mask weight pack: oc 0..17 = offw, 18..26 = maskw, rest 0
// ===========================================================================
__global__ void owpack_kernel(const float* __restrict__ offw,
                              const float* __restrict__ maskw) {
    int i2 = blockIdx.x * blockDim.x + threadIdx.x;
    if (i2 >= K2_*32*C_/2) return;
    int cp  = i2 & 63;
    int oc  = (i2 >> 6) & 31;
    int k2  = i2 >> 11;
    int c = cp * 2;
    float v0 = 0.f, v1 = 0.f;
    if (oc < 18) {
        v0 = offw[oc*E_ + c*K2_ + k2];
        v1 = offw[oc*E_ + (c+1)*K2_ + k2];
    } else if (oc < 27) {
        v0 = maskw[(oc-18)*E_ + c*K2_ + k2];
        v1 = maskw[(oc-18)*E_ + (c+1)*K2_ + k2];
    }
    uint32_t hi, lo;
    split2(v0, v1, hi, lo);
    g_owhi[i2] = hi;
    g_owlo[i2] = lo;
}

// ===========================================================================
// Kernel B: offset+mask conv via HMMA, cp.async double-buffered over k2.
// Block = 128 pixels (2 rows) x 32 oc. Slot: A hi/lo (2x34816) + B hi/lo.
// ===========================================================================
#define OM_SLOT 87040
#define OM_A_HI 0
#define OM_A_LO 34816
#define OM_B_HI 69632
#define OM_B_LO 78336
#define OM_BIAS (2*OM_SLOT)          // 174080
#define OM_TOTAL (2*OM_SLOT + 128)   // 174208

__global__ void __launch_bounds__(256, 1) offmask_mma_kernel(
    const float* __restrict__ offb, const float* __restrict__ maskb) {
    extern __shared__ char smem[];
    uint32_t sb = smem_u32(smem);
    const int t    = threadIdx.x;
    const int lane = t & 31;
    const int wid  = t >> 5;
    const int bi   = blockIdx.x;     // 256
    const int b    = bi >> 5;
    const int rp   = bi & 31;

    float* bias_s = (float*)(smem + OM_BIAS);
    if (t < 32)
        bias_s[t] = (t < 18) ? offb[t] : (t < 27 ? maskb[t-18] : 0.f);

    const uint32_t aOff = (uint32_t)((wid*16 + (lane & 15))*272 + (lane >> 4)*16);
    const uint32_t bOff = (uint32_t)((lane & 7)*272 + ((lane >> 3) & 1)*16);

    float acc[4][4];
    #pragma unroll
    for (int i = 0; i < 4; i++)
        #pragma unroll
        for (int j = 0; j < 4; j++) acc[i][j] = 0.f;

    // A staging mapping: 2 threads per pixel
    const int m    = t >> 1;
    const int half = t & 1;
    const int row  = rp*2 + (m >> 6);
    const int col  = m & 63;

    // ---- staging lambda: issue cp.asyncs for chunk k2 into slot k2&1 ----
    auto stage = [&](int k2) {
        uint32_t slot = (uint32_t)((k2 & 1) * OM_SLOT);
        // B chunk: 512 x 16B (hi) + 512 (lo), 2+2 per thread
        #pragma unroll
        for (int it = 0; it < 2; it++) {
            int idx = it*256 + t;            // 0..511
            int oc = idx >> 4;
            int g  = idx & 15;
            int gi = k2*2048 + oc*64 + g*4;
            uint32_t so = slot + (uint32_t)(oc*272 + g*16);
            CP_A16(sb + OM_B_HI + so, &g_owhi[gi]);
            CP_A16(sb + OM_B_LO + so, &g_owlo[gi]);
        }
        // A chunk: im2col with zero-fill for out-of-range
        int ki = k2 / 3, kj = k2 - ki*3;
        int sy = row - 1 + ki;
        int sx = col - 1 + kj;
        bool valid = (sy >= 0) && (sy < H_) && (sx >= 0) && (sx < W_);
        uint32_t sz = valid ? 16u : 0u;
        int syc = valid ? sy : 0;
        int sxc = valid ? sx : 0;
        int gb = ((b*H_ + syc)*W_ + sxc)*64 + half*32;
        uint32_t abase = slot + (uint32_t)(m*272 + half*128);
        #pragma unroll
        for (int j4 = 0; j4 < 8; j4++) {
            CP_A16Z(sb + OM_A_HI + abase + j4*16, &g_xhi[gb + j4*4], sz);
            CP_A16Z(sb + OM_A_LO + abase + j4*16, &g_xlo[gb + j4*4], sz);
        }
        CP_COMMIT();
    };

    stage(0);
    for (int k2 = 0; k2 < K2_; k2++) {
        if (k2 < K2_-1) { stage(k2+1); CP_WAIT(1); }
        else           { CP_WAIT(0); }
        __syncthreads();

        uint32_t slot = (uint32_t)((k2 & 1) * OM_SLOT);
        #pragma unroll
        for (int pass = 0; pass < 3; pass++) {
            uint32_t ab = sb + slot + ((pass == 2) ? OM_A_LO : OM_A_HI) + aOff;
            uint32_t bb = sb + slot + ((pass == 1) ? OM_B_LO : OM_B_HI) + bOff;
            #pragma unroll
            for (int ks = 0; ks < 8; ks++) {
                uint32_t afr[4];
                ldsm4(afr, ab + ks*32);
                #pragma unroll
                for (int nt = 0; nt < 4; nt++) {
                    uint32_t bfr[2];
                    ldsm2(bfr, bb + nt*2176 + ks*32);
                    mma16816(acc[nt], afr, bfr);
                }
            }
        }
        __syncthreads();
    }

    // epilogue: bias + sigmoid, scatter
    const int r0  = lane >> 2;
    const int cl0 = (lane & 3)*2;
    #pragma unroll
    for (int nt = 0; nt < 4; nt++) {
        #pragma unroll
        for (int j = 0; j < 4; j++) {
            int oc = nt*8 + cl0 + (j & 1);
            if (oc >= 27) continue;
            int pl   = wid*16 + r0 + (j >> 1)*8;
            int prow = rp*2 + (pl >> 6);
            int pcol = pl & 63;
            int gpix = (b*H_ + prow)*W_ + pcol;
            float v = acc[nt][j] + bias_s[oc];
            if (oc >= 18) v = 1.f / (1.f + expf(-v));
            g_offmask[gpix*27 + oc] = v;
        }
    }
}

// ===========================================================================
// Kernel S: sample cols to gmem. One warp per (pixel, k2) task.
// ===========================================================================
__global__ void __launch_bounds__(256) sample_cols_kernel() {
    int task = blockIdx.x * 8 + (threadIdx.x >> 5);
    int lane = threadIdx.x & 31;
    int pix = task / 9;
    int k2  = task - pix*9;
    int b   = pix >> 12;
    int rem = pix & 4095;
    int row = rem >> 6;
    int col = rem & 63;

    float offy = g_offmask[pix*27 + 2*k2];
    float offx = g_offmask[pix*27 + 2*k2 + 1];
    float msk  = g_offmask[pix*27 + 18 + k2];
    int ki = k2 / 3, kj = k2 - ki*3;
    float py = (float)(row - 1 + ki) + offy;
    float px = (float)(col - 1 + kj) + offx;
    float y0f = floorf(py), x0f = floorf(px);
    float ly = py - y0f, lx = px - x0f;
    int y0 = (int)y0f, x0 = (int)x0f;
    float w00 = (1.f-ly)*(1.f-lx)*msk;
    float w01 = (1.f-ly)*lx*msk;
    float w10 = ly*(1.f-lx)*msk;
    float w11 = ly*lx*msk;
    bool vy0 = (y0 >= 0) && (y0 < H_);
    bool vy1 = (y0+1 >= 0) && (y0+1 < H_);
    bool vx0 = (x0 >= 0) && (x0 < W_);
    bool vx1 = (x0+1 >= 0) && (x0+1 < W_);
    bool p00 = vy0 && vx0, p01 = vy0 && vx1;
    bool p10 = vy1 && vx0, p11 = vy1 && vx1;
    const float4* xb4 = (const float4*)g_xT + (size_t)b * H_ * W_ * 32;
    int i00 = (y0*W_ + x0)*32 + lane;
    float4 zero = make_float4(0.f, 0.f, 0.f, 0.f);
    float4 v00 = p00 ? xb4[i00           ] : zero;
    float4 v01 = p01 ? xb4[i00 + 32      ] : zero;
    float4 v10 = p10 ? xb4[i00 + W_*32   ] : zero;
    float4 v11 = p11 ? xb4[i00 + W_*32+32] : zero;
    float r0 = w00*v00.x + w01*v01.x + w10*v10.x + w11*v11.x;
    float r1 = w00*v00.y + w01*v01.y + w10*v10.y + w11*v11.y;
    float r2 = w00*v00.z + w01*v01.z + w10*v10.z + w11*v11.z;
    float r3 = w00*v00.w + w01*v01.w + w10*v10.w + w11*v11.w;
    uint32_t hi01, lo01, hi23, lo23;
    split2(r0, r1, hi01, lo01);
    split2(r2, r3, hi23, lo23);
    int o = pix*PITCH + k2*64 + lane*2;
    *(uint2*)&g_colhi[o] = make_uint2(hi01, hi23);
    *(uint2*)&g_collo[o] = make_uint2(lo01, lo23);
}

// ===========================================================================
// Kernel C: pure GEMM, cp.async double-buffered over 18 K-subchunks.
// Block = 128 pix x 128 oc (grid 256), 8 warps (64x32 warp tile).
// ===========================================================================
#define G_SLOT 73728
#define G_A_HI 0
#define G_A_LO 18432
#define G_W_HI 36864
#define G_W_LO 55296
#define G_TOTAL (2*G_SLOT)    // 147456

__global__ void __launch_bounds__(256, 1) dcn_gemm_kernel(float* __restrict__ out) {
    extern __shared__ char smem[];
    uint32_t sb = smem_u32(smem);
    const int t    = threadIdx.x;
    const int lane = t & 31;
    const int wid  = t >> 5;
    const int bi   = blockIdx.x;    // 256 blocks
    const int b    = bi >> 5;
    const int rp   = bi & 31;

    const int warp_m = wid & 1;
    const int warp_n = wid >> 1;
    const uint32_t a_off = (uint32_t)((warp_m*64 + (lane & 15))*144 + (lane >> 4)*16);
    const uint32_t b_off = (uint32_t)((warp_n*32 + (lane & 7))*144 + ((lane >> 3) & 1)*16);

    float acc[4][4][4];
    #pragma unroll
    for (int i = 0; i < 4; i++)
        #pragma unroll
        for (int j = 0; j < 4; j++)
            #pragma unroll
            for (int k = 0; k < 4; k++) acc[i][j][k] = 0.f;

    // A staging: 2 threads per pixel
    const int sp = t >> 1;
    const int sh = t & 1;
    const int gA = (bi*128 + sp) * PITCH + sh*16;

    auto stage = [&](int sub) {
        uint32_t slot = (uint32_t)((sub & 1) * G_SLOT);
        uint32_t aso = slot + (uint32_t)(sp*144 + sh*64);
        int gsrc = gA + sub*32;
        #pragma unroll
        for (int j = 0; j < 4; j++) {
            CP_A16(sb + G_A_HI + aso + j*16, &g_colhi[gsrc + j*4]);
            CP_A16(sb + G_A_LO + aso + j*16, &g_collo[gsrc + j*4]);
        }
        int k2 = sub >> 1, ch = sub & 1;
        #pragma unroll
        for (int it = 0; it < 4; it++) {
            int idx = it*256 + t;           // 0..1023
            int oc = idx >> 3;
            int g  = idx & 7;
            int gi = k2*8192 + oc*64 + ch*32 + g*4;
            uint32_t so = slot + (uint32_t)(oc*144 + g*16);
            CP_A16(sb + G_W_HI + so, &g_whi[gi]);
            CP_A16(sb + G_W_LO + so, &g_wlo[gi]);
        }
        CP_COMMIT();
    };

    stage(0);
    for (int sub = 0; sub < 18; sub++) {
        if (sub < 17) { stage(sub+1); CP_WAIT(1); }
        else          { CP_WAIT(0); }
        __syncthreads();

        uint32_t slot = (uint32_t)((sub & 1) * G_SLOT);
        #pragma unroll
        for (int pass = 0; pass < 3; pass++) {
            uint32_t ab = sb + slot + ((pass == 2) ? G_A_LO : G_A_HI) + a_off;
            uint32_t bb = sb + slot + ((pass == 1) ? G_W_LO : G_W_HI) + b_off;
            #pragma unroll
            for (int ks = 0; ks < 4; ks++) {
                uint32_t afr[4][4];
                uint32_t bfr[4][2];
                #pragma unroll
                for (int mt = 0; mt < 4; mt++)
                    ldsm4(afr[mt], ab + mt*2304 + ks*32);
                #pragma unroll
                for (int nt = 0; nt < 4; nt++)
                    ldsm2(bfr[nt], bb + nt*1152 + ks*32);
                #pragma unroll
                for (int mt = 0; mt < 4; mt++)
                    #pragma unroll
                    for (int nt = 0; nt < 4; nt++)
                        mma16816(acc[mt][nt], afr[mt], bfr[nt]);
            }
        }
        __syncthreads();
    }

    // ---- epilogue: transpose through smem, coalesced NCHW stores ----
    float* O_s = (float*)smem;     // [oc][pix], stride 132 (67,584 B < smem)
    const int g   = lane >> 2;
    const int tig = lane & 3;
    #pragma unroll
    for (int mt = 0; mt < 4; mt++) {
        #pragma unroll
        for (int nt = 0; nt < 4; nt++) {
            int p0 = warp_m*64 + mt*16 + g;
            int o0 = warp_n*32 + nt*8 + tig*2;
            O_s[(o0  )*132 + p0    ] = acc[mt][nt][0];
            O_s[(o0+1)*132 + p0    ] = acc[mt][nt][1];
            O_s[(o0  )*132 + p0 + 8] = acc[mt][nt][2];
            O_s[(o0+1)*132 + p0 + 8] = acc[mt][nt][3];
        }
    }
    __syncthreads();
    #pragma unroll 4
    for (int it = 0; it < 64; it++) {
        int idx = it*256 + t;
        int oc = idx >> 7;
        int p  = idx & 127;
        out[(((size_t)b*O_ + oc)*H_ + rp*2 + (p >> 6))*W_ + (p & 63)] =
            O_s[oc*132 + p];
    }
}

// ===========================================================================
extern "C" void kernel_launch(void* const* d_in, const int* in_sizes, int n_in,
                              void* d_out, int out_size) {
    const float* x      = (const float*)d_in[0];
    const float* weight = (const float*)d_in[1];
    const float* offw   = (const float*)d_in[2];
    const float* offb   = (const float*)d_in[3];
    const float* maskw  = (const float*)d_in[4];
    const float* maskb  = (const float*)d_in[5];
    float* out = (float*)d_out;

    static bool attr_set = false;
    if (!attr_set) {
        cudaFuncSetAttribute(offmask_mma_kernel,
            cudaFuncAttributeMaxDynamicSharedMemorySize, OM_TOTAL);
        cudaFuncSetAttribute(dcn_gemm_kernel,
            cudaFuncAttributeMaxDynamicSharedMemorySize, G_TOTAL);
        attr_set = true;
    }

    transpose_kernel<<<B_*H_*4, 256>>>(x);
    wsplit_kernel<<<(K2_*O_*C_/2 + 255)/256, 256>>>(weight);
    owpack_kernel<<<(K2_*32*C_/2 + 255)/256, 256>>>(offw, maskw);
    offmask_mma_kernel<<<256, 256, OM_TOTAL>>>(offb, maskb);
    sample_cols_kernel<<<NPIX*K2_/8, 256>>>();
    dcn_gemm_kernel<<<256, 256, G_TOTAL>>>(out);
}

// round 10
// speedup vs baseline: 4.2538x; 1.0516x over previous
#include <cuda_runtime.h>
#include <cuda_bf16.h>
#include <math.h>
#include <stdint.h>

// Problem constants
#define B_  8
#define C_  128
#define H_  64
#define W_  64
#define O_  128
#define K2_ 9
#define E_  1152   // C_*K2_
#define NPIX (B_*H_*W_)      // 32768
#define PITCH 576            // u32 per pixel row of cols (1152 bf16 / 2)

// Scratch (device globals; no allocation allowed)
__device__ float    g_xT [B_*H_*W_*C_];      // NHWC fp32
__device__ uint32_t g_xhi[B_*H_*W_*C_/2];    // NHWC bf16x2 hi split
__device__ uint32_t g_xlo[B_*H_*W_*C_/2];    // NHWC bf16x2 lo split
__device__ float    g_offmask[NPIX*27];      // 18 offsets + 9 sigmoided masks / pixel
__device__ uint32_t g_whi[K2_*O_*C_/2];      // main weight hi, [k2][oc][c/2]
__device__ uint32_t g_wlo[K2_*O_*C_/2];      // main weight lo
__device__ uint32_t g_owhi[K2_*32*C_/2];     // offset/mask weight hi
__device__ uint32_t g_owlo[K2_*32*C_/2];     // offset/mask weight lo
__device__ uint32_t g_colhi[NPIX*PITCH];     // sampled cols hi, [pix][k2][c/2]
__device__ uint32_t g_collo[NPIX*PITCH];     // sampled cols lo

// ===========================================================================
// Helpers (baseline PTX: ldmatrix + mma.sync + cp.async)
// ===========================================================================
__device__ __forceinline__ uint32_t smem_u32(const void* p) {
    uint32_t a;
    asm("{ .reg .u64 t; cvta.to.shared.u64 t, %1; cvt.u32.u64 %0, t; }"
        : "=r"(a) : "l"(p));
    return a;
}
__device__ __forceinline__ void ldsm4(uint32_t* r, uint32_t addr) {
    asm volatile("ldmatrix.sync.aligned.m8n8.x4.shared.b16 {%0,%1,%2,%3}, [%4];"
        : "=r"(r[0]), "=r"(r[1]), "=r"(r[2]), "=r"(r[3]) : "r"(addr));
}
__device__ __forceinline__ void ldsm2(uint32_t* r, uint32_t addr) {
    asm volatile("ldmatrix.sync.aligned.m8n8.x2.shared.b16 {%0,%1}, [%2];"
        : "=r"(r[0]), "=r"(r[1]) : "r"(addr));
}
__device__ __forceinline__ void mma16816(float* c, const uint32_t* a, const uint32_t* b) {
    asm volatile(
        "mma.sync.aligned.m16n8k16.row.col.f32.bf16.bf16.f32 "
        "{%0,%1,%2,%3}, {%4,%5,%6,%7}, {%8,%9}, {%0,%1,%2,%3};"
        : "+f"(c[0]), "+f"(c[1]), "+f"(c[2]), "+f"(c[3])
        : "r"(a[0]), "r"(a[1]), "r"(a[2]), "r"(a[3]), "r"(b[0]), "r"(b[1]));
}
#define CP_A16(dst, src) \
    asm volatile("cp.async.cg.shared.global [%0], [%1], 16;" \
                 :: "r"(dst), "l"(src))
#define CP_A16Z(dst, src, sz) \
    asm volatile("cp.async.cg.shared.global [%0], [%1], 16, %2;" \
                 :: "r"(dst), "l"(src), "r"(sz))
#define CP_COMMIT() asm volatile("cp.async.commit_group;")
#define CP_WAIT(n)  asm volatile("cp.async.wait_group %0;" :: "n"(n))

__device__ __forceinline__ uint32_t packbf(__nv_bfloat16 a, __nv_bfloat16 b) {
    __nv_bfloat162 t(a, b);
    return *(uint32_t*)&t;
}
__device__ __forceinline__ void split2(float v0, float v1, uint32_t& hi, uint32_t& lo) {
    __nv_bfloat16 h0 = __float2bfloat16(v0);
    __nv_bfloat16 h1 = __float2bfloat16(v1);
    __nv_bfloat16 l0 = __float2bfloat16(v0 - __bfloat162float(h0));
    __nv_bfloat16 l1 = __float2bfloat16(v1 - __bfloat162float(h1));
    hi = packbf(h0, h1);
    lo = packbf(l0, l1);
}

// ===========================================================================
// Kernel A: NCHW -> NHWC transpose + bf16 hi/lo split (smem tile, coalesced)
// ===========================================================================
__global__ void __launch_bounds__(256) transpose_kernel(const float* __restrict__ x) {
    __shared__ float ts[32][65];
    int bi  = blockIdx.x;
    int ct  = bi & 3;
    int rem = bi >> 2;
    int y   = rem & 63;
    int b   = rem >> 6;
    int c0  = ct * 32;
    int t   = threadIdx.x;

    #pragma unroll
    for (int it = 0; it < 8; it++) {
        int idx = it*256 + t;
        int cl = idx >> 6, xw = idx & 63;
        ts[cl][xw] = x[((b*C_ + c0 + cl)*H_ + y)*W_ + xw];
    }
    __syncthreads();
    #pragma unroll
    for (int it = 0; it < 8; it++) {
        int idx = it*256 + t;
        int cl = idx & 31, xw = idx >> 5;
        g_xT[((b*H_ + y)*W_ + xw)*C_ + c0 + cl] = ts[cl][xw];
    }
    #pragma unroll
    for (int it = 0; it < 4; it++) {
        int idx = it*256 + t;
        int cp = idx & 15, xw = idx >> 4;
        uint32_t hi, lo;
        split2(ts[cp*2][xw], ts[cp*2 + 1][xw], hi, lo);
        int o = ((b*H_ + y)*W_ + xw)*64 + (c0 >> 1) + cp;
        g_xhi[o] = hi;
        g_xlo[o] = lo;
    }
}

// ===========================================================================
// Kernel A2: main weight hi/lo split into [k2][oc][c] bf16x2
// ===========================================================================
__global__ void wsplit_kernel(const float* __restrict__ w) {
    int i2 = blockIdx.x * blockDim.x + threadIdx.x;
    if (i2 >= K2_*O_*C_/2) return;
    int cpair = i2 & 63;
    int oc    = (i2 >> 6) & 127;
    int k2    = i2 >> 13;
    int c = cpair * 2;
    uint32_t hi, lo;
    split2(w[oc*E_ + c*K2_ + k2], w[oc*E_ + (c+1)*K2_ + k2], hi, lo);
    g_whi[i2] = hi;
    g_wlo[i2] = lo;
}

// ===========================================================================
// Kernel A3: offset/mask weight pack
// ===========================================================================
__global__ void owpack_kernel(const float* __restrict__ offw,
                              const float* __restrict__ maskw) {
    int i2 = blockIdx.x * blockDim.x + threadIdx.x;
    if (i2 >= K2_*32*C_/2) return;
    int cp  = i2 & 63;
    int oc  = (i2 >> 6) & 31;
    int k2  = i2 >> 11;
    int c = cp * 2;
    float v0 = 0.f, v1 = 0.f;
    if (oc < 18) {
        v0 = offw[oc*E_ + c*K2_ + k2];
        v1 = offw[oc*E_ + (c+1)*K2_ + k2];
    } else if (oc < 27) {
        v0 = maskw[(oc-18)*E_ + c*K2_ + k2];
        v1 = maskw[(oc-18)*E_ + (c+1)*K2_ + k2];
    }
    uint32_t hi, lo;
    split2(v0, v1, hi, lo);
    g_owhi[i2] = hi;
    g_owlo[i2] = lo;
}

// ===========================================================================
// Kernel B: offset+mask conv via HMMA, cp.async double-buffered, 512 threads.
// Block = 128 pixels x 32 oc, 16 warps (warp tile 16 pix x 16 oc).
// ===========================================================================
#define OM_SLOT 87040
#define OM_A_HI 0
#define OM_A_LO 34816
#define OM_B_HI 69632
#define OM_B_LO 78336
#define OM_BIAS (2*OM_SLOT)          // 174080
#define OM_TOTAL (2*OM_SLOT + 128)   // 174208

__global__ void __launch_bounds__(512, 1) offmask_mma_kernel(
    const float* __restrict__ offb, const float* __restrict__ maskb) {
    extern __shared__ char smem[];
    uint32_t sb = smem_u32(smem);
    const int t    = threadIdx.x;
    const int lane = t & 31;
    const int wid  = t >> 5;        // 0..15
    const int bi   = blockIdx.x;     // 256
    const int b    = bi >> 5;
    const int rp   = bi & 31;

    float* bias_s = (float*)(smem + OM_BIAS);
    if (t < 32)
        bias_s[t] = (t < 18) ? offb[t] : (t < 27 ? maskb[t-18] : 0.f);

    const int warp_m = wid >> 1;    // 8 groups of 16 pixels
    const int warp_n = wid & 1;     // 2 groups of 16 oc
    const uint32_t aOff = (uint32_t)((warp_m*16 + (lane & 15))*272 + (lane >> 4)*16);
    const uint32_t bOff = (uint32_t)((warp_n*16 + (lane & 7))*272 + ((lane >> 3) & 1)*16);

    float acc[2][4];
    #pragma unroll
    for (int i = 0; i < 2; i++)
        #pragma unroll
        for (int j = 0; j < 4; j++) acc[i][j] = 0.f;

    // A staging: 4 threads per pixel (quarters of the 64-u32 row)
    const int m   = t >> 2;         // pixel 0..127
    const int q   = t & 3;          // quarter
    const int row = rp*2 + (m >> 6);
    const int col = m & 63;

    auto stage = [&](int k2) {
        uint32_t slot = (uint32_t)((k2 & 1) * OM_SLOT);
        // B chunk: 2048 u32 per buffer / 512 threads = 1 uint4 each
        {
            int oc = t >> 4;
            int g  = t & 15;
            int gi = k2*2048 + oc*64 + g*4;
            uint32_t so = slot + (uint32_t)(oc*272 + g*16);
            CP_A16(sb + OM_B_HI + so, &g_owhi[gi]);
            CP_A16(sb + OM_B_LO + so, &g_owlo[gi]);
        }
        // A chunk: im2col with zero-fill
        int ki = k2 / 3, kj = k2 - ki*3;
        int sy = row - 1 + ki;
        int sx = col - 1 + kj;
        bool valid = (sy >= 0) && (sy < H_) && (sx >= 0) && (sx < W_);
        uint32_t sz = valid ? 16u : 0u;
        int syc = valid ? sy : 0;
        int sxc = valid ? sx : 0;
        int gb = ((b*H_ + syc)*W_ + sxc)*64 + q*16;
        uint32_t abase = slot + (uint32_t)(m*272 + q*64);
        #pragma unroll
        for (int j4 = 0; j4 < 4; j4++) {
            CP_A16Z(sb + OM_A_HI + abase + j4*16, &g_xhi[gb + j4*4], sz);
            CP_A16Z(sb + OM_A_LO + abase + j4*16, &g_xlo[gb + j4*4], sz);
        }
        CP_COMMIT();
    };

    stage(0);
    for (int k2 = 0; k2 < K2_; k2++) {
        if (k2 < K2_-1) { stage(k2+1); CP_WAIT(1); }
        else           { CP_WAIT(0); }
        __syncthreads();

        uint32_t slot = (uint32_t)((k2 & 1) * OM_SLOT);
        #pragma unroll
        for (int pass = 0; pass < 3; pass++) {
            uint32_t ab = sb + slot + ((pass == 2) ? OM_A_LO : OM_A_HI) + aOff;
            uint32_t bb = sb + slot + ((pass == 1) ? OM_B_LO : OM_B_HI) + bOff;
            #pragma unroll
            for (int ks = 0; ks < 8; ks++) {
                uint32_t afr[4];
                ldsm4(afr, ab + ks*32);
                #pragma unroll
                for (int nt = 0; nt < 2; nt++) {
                    uint32_t bfr[2];
                    ldsm2(bfr, bb + nt*2176 + ks*32);
                    mma16816(acc[nt], afr, bfr);
                }
            }
        }
        __syncthreads();
    }

    // epilogue: bias + sigmoid, scatter
    const int r0  = lane >> 2;
    const int cl0 = (lane & 3)*2;
    #pragma unroll
    for (int nt = 0; nt < 2; nt++) {
        #pragma unroll
        for (int j = 0; j < 4; j++) {
            int oc = warp_n*16 + nt*8 + cl0 + (j & 1);
            if (oc >= 27) continue;
            int pl   = warp_m*16 + r0 + (j >> 1)*8;
            int prow = rp*2 + (pl >> 6);
            int pcol = pl & 63;
            int gpix = (b*H_ + prow)*W_ + pcol;
            float v = acc[nt][j] + bias_s[oc];
            if (oc >= 18) v = 1.f / (1.f + expf(-v));
            g_offmask[gpix*27 + oc] = v;
        }
    }
}

// ===========================================================================
// Kernel S: sample cols to gmem. One warp per (pixel, k2) task.
// ===========================================================================
__global__ void __launch_bounds__(256) sample_cols_kernel() {
    int task = blockIdx.x * 8 + (threadIdx.x >> 5);
    int lane = threadIdx.x & 31;
    int pix = task / 9;
    int k2  = task - pix*9;
    int b   = pix >> 12;
    int rem = pix & 4095;
    int row = rem >> 6;
    int col = rem & 63;

    float offy = g_offmask[pix*27 + 2*k2];
    float offx = g_offmask[pix*27 + 2*k2 + 1];
    float msk  = g_offmask[pix*27 + 18 + k2];
    int ki = k2 / 3, kj = k2 - ki*3;
    float py = (float)(row - 1 + ki) + offy;
    float px = (float)(col - 1 + kj) + offx;
    float y0f = floorf(py), x0f = floorf(px);
    float ly = py - y0f, lx = px - x0f;
    int y0 = (int)y0f, x0 = (int)x0f;
    float w00 = (1.f-ly)*(1.f-lx)*msk;
    float w01 = (1.f-ly)*lx*msk;
    float w10 = ly*(1.f-lx)*msk;
    float w11 = ly*lx*msk;
    bool vy0 = (y0 >= 0) && (y0 < H_);
    bool vy1 = (y0+1 >= 0) && (y0+1 < H_);
    bool vx0 = (x0 >= 0) && (x0 < W_);
    bool vx1 = (x0+1 >= 0) && (x0+1 < W_);
    bool p00 = vy0 && vx0, p01 = vy0 && vx1;
    bool p10 = vy1 && vx0, p11 = vy1 && vx1;
    const float4* xb4 = (const float4*)g_xT + (size_t)b * H_ * W_ * 32;
    int i00 = (y0*W_ + x0)*32 + lane;
    float4 zero = make_float4(0.f, 0.f, 0.f, 0.f);
    float4 v00 = p00 ? xb4[i00           ] : zero;
    float4 v01 = p01 ? xb4[i00 + 32      ] : zero;
    float4 v10 = p10 ? xb4[i00 + W_*32   ] : zero;
    float4 v11 = p11 ? xb4[i00 + W_*32+32] : zero;
    float r0 = w00*v00.x + w01*v01.x + w10*v10.x + w11*v11.x;
    float r1 = w00*v00.y + w01*v01.y + w10*v10.y + w11*v11.y;
    float r2 = w00*v00.z + w01*v01.z + w10*v10.z + w11*v11.z;
    float r3 = w00*v00.w + w01*v01.w + w10*v10.w + w11*v11.w;
    uint32_t hi01, lo01, hi23, lo23;
    split2(r0, r1, hi01, lo01);
    split2(r2, r3, hi23, lo23);
    int o = pix*PITCH + k2*64 + lane*2;
    *(uint2*)&g_colhi[o] = make_uint2(hi01, hi23);
    *(uint2*)&g_collo[o] = make_uint2(lo01, lo23);
}

// ===========================================================================
// Kernel C: pure GEMM, cp.async double-buffered, 512 threads.
// Block = 128 pix x 128 oc (grid 256), 16 warps (warp tile 32 pix x 32 oc).
// ===========================================================================
#define G_SLOT 73728
#define G_A_HI 0
#define G_A_LO 18432
#define G_W_HI 36864
#define G_W_LO 55296
#define G_TOTAL (2*G_SLOT)    // 147456

__global__ void __launch_bounds__(512, 1) dcn_gemm_kernel(float* __restrict__ out) {
    extern __shared__ char smem[];
    uint32_t sb = smem_u32(smem);
    const int t    = threadIdx.x;
    const int lane = t & 31;
    const int wid  = t >> 5;        // 0..15
    const int bi   = blockIdx.x;    // 256 blocks
    const int b    = bi >> 5;
    const int rp   = bi & 31;

    const int warp_m = wid & 3;     // 4 groups of 32 pixels
    const int warp_n = wid >> 2;    // 4 groups of 32 oc
    const uint32_t a_off = (uint32_t)((warp_m*32 + (lane & 15))*144 + (lane >> 4)*16);
    const uint32_t b_off = (uint32_t)((warp_n*32 + (lane & 7))*144 + ((lane >> 3) & 1)*16);

    float acc[2][4][4];
    #pragma unroll
    for (int i = 0; i < 2; i++)
        #pragma unroll
        for (int j = 0; j < 4; j++)
            #pragma unroll
            for (int k = 0; k < 4; k++) acc[i][j][k] = 0.f;

    // A staging: 4 threads per pixel (quarters of the 32-u32 sub-row)
    const int sp = t >> 2;          // pixel 0..127
    const int sq = t & 3;
    const int gA = (bi*128 + sp) * PITCH + sq*8;

    auto stage = [&](int sub) {
        uint32_t slot = (uint32_t)((sub & 1) * G_SLOT);
        uint32_t aso = slot + (uint32_t)(sp*144 + sq*32);
        int gsrc = gA + sub*32;
        #pragma unroll
        for (int j = 0; j < 2; j++) {
            CP_A16(sb + G_A_HI + aso + j*16, &g_colhi[gsrc + j*4]);
            CP_A16(sb + G_A_LO + aso + j*16, &g_collo[gsrc + j*4]);
        }
        int k2 = sub >> 1, ch = sub & 1;
        #pragma unroll
        for (int it = 0; it < 2; it++) {
            int idx = it*512 + t;           // 0..1023
            int oc = idx >> 3;
            int g  = idx & 7;
            int gi = k2*8192 + oc*64 + ch*32 + g*4;
            uint32_t so = slot + (uint32_t)(oc*144 + g*16);
            CP_A16(sb + G_W_HI + so, &g_whi[gi]);
            CP_A16(sb + G_W_LO + so, &g_wlo[gi]);
        }
        CP_COMMIT();
    };

    stage(0);
    for (int sub = 0; sub < 18; sub++) {
        if (sub < 17) { stage(sub+1); CP_WAIT(1); }
        else          { CP_WAIT(0); }
        __syncthreads();

        uint32_t slot = (uint32_t)((sub & 1) * G_SLOT);
        #pragma unroll
        for (int pass = 0; pass < 3; pass++) {
            uint32_t ab = sb + slot + ((pass == 2) ? G_A_LO : G_A_HI) + a_off;
            uint32_t bb = sb + slot + ((pass == 1) ? G_W_LO : G_W_HI) + b_off;
            #pragma unroll
            for (int ks = 0; ks < 4; ks++) {
                uint32_t afr[2][4];
                uint32_t bfr[4][2];
                #pragma unroll
                for (int mt = 0; mt < 2; mt++)
                    ldsm4(afr[mt], ab + mt*2304 + ks*32);
                #pragma unroll
                for (int nt = 0; nt < 4; nt++)
                    ldsm2(bfr[nt], bb + nt*1152 + ks*32);
                #pragma unroll
                for (int mt = 0; mt < 2; mt++)
                    #pragma unroll
                    for (int nt = 0; nt < 4; nt++)
                        mma16816(acc[mt][nt], afr[mt], bfr[nt]);
            }
        }
        __syncthreads();
    }

    // ---- epilogue: transpose through smem, coalesced NCHW stores ----
    float* O_s = (float*)smem;     // [oc][pix], stride 132 (67,584 B)
    const int g   = lane >> 2;
    const int tig = lane & 3;
    #pragma unroll
    for (int mt = 0; mt < 2; mt++) {
        #pragma unroll
        for (int nt = 0; nt < 4; nt++) {
            int p0 = warp_m*32 + mt*16 + g;
            int o0 = warp_n*32 + nt*8 + tig*2;
            O_s[(o0  )*132 + p0    ] = acc[mt][nt][0];
            O_s[(o0+1)*132 + p0    ] = acc[mt][nt][1];
            O_s[(o0  )*132 + p0 + 8] = acc[mt][nt][2];
            O_s[(o0+1)*132 + p0 + 8] = acc[mt][nt][3];
        }
    }
    __syncthreads();
    // 16384 / 512 = 32 iterations
    #pragma unroll 4
    for (int it = 0; it < 32; it++) {
        int idx = it*512 + t;
        int oc = idx >> 7;
        int p  = idx & 127;
        out[(((size_t)b*O_ + oc)*H_ + rp*2 + (p >> 6))*W_ + (p & 63)] =
            O_s[oc*132 + p];
    }
}

// ===========================================================================
extern "C" void kernel_launch(void* const* d_in, const int* in_sizes, int n_in,
                              void* d_out, int out_size) {
    const float* x      = (const float*)d_in[0];
    const float* weight = (const float*)d_in[1];
    const float* offw   = (const float*)d_in[2];
    const float* offb   = (const float*)d_in[3];
    const float* maskw  = (const float*)d_in[4];
    const float* maskb  = (const float*)d_in[5];
    float* out = (float*)d_out;

    static bool attr_set = false;
    if (!attr_set) {
        cudaFuncSetAttribute(offmask_mma_kernel,
            cudaFuncAttributeMaxDynamicSharedMemorySize, OM_TOTAL);
        cudaFuncSetAttribute(dcn_gemm_kernel,
            cudaFuncAttributeMaxDynamicSharedMemorySize, G_TOTAL);
        attr_set = true;
    }

    transpose_kernel<<<B_*H_*4, 256>>>(x);
    wsplit_kernel<<<(K2_*O_*C_/2 + 255)/256, 256>>>(weight);
    owpack_kernel<<<(K2_*32*C_/2 + 255)/256, 256>>>(offw, maskw);
    offmask_mma_kernel<<<256, 512, OM_TOTAL>>>(offb, maskb);
    sample_cols_kernel<<<NPIX*K2_/8, 256>>>();
    dcn_gemm_kernel<<<256, 512, G_TOTAL>>>(out);
}

// round 11
// speedup vs baseline: 4.3394x; 1.0201x over previous
#include <cuda_runtime.h>
#include <cuda_bf16.h>
#include <math.h>
#include <stdint.h>

// Problem constants
#define B_  8
#define C_  128
#define H_  64
#define W_  64
#define O_  128
#define K2_ 9
#define E_  1152   // C_*K2_
#define NPIX (B_*H_*W_)      // 32768
#define PITCH 576            // u32 per pixel row of cols (1152 bf16 / 2)

// Scratch (device globals; no allocation allowed)
__device__ float    g_xT [B_*H_*W_*C_];      // NHWC fp32
__device__ uint32_t g_xhi[B_*H_*W_*C_/2];    // NHWC bf16x2 hi split
__device__ uint32_t g_xlo[B_*H_*W_*C_/2];    // NHWC bf16x2 lo split
__device__ float    g_offmask[NPIX*27];      // 18 offsets + 9 sigmoided masks / pixel
__device__ uint32_t g_whi[K2_*O_*C_/2];      // main weight hi, [k2][oc][c/2]
__device__ uint32_t g_wlo[K2_*O_*C_/2];      // main weight lo
__device__ uint32_t g_owhi[K2_*32*C_/2];     // offset/mask weight hi
__device__ uint32_t g_owlo[K2_*32*C_/2];     // offset/mask weight lo
__device__ uint32_t g_colhi[NPIX*PITCH];     // sampled cols hi, [pix][k2][c/2]
__device__ uint32_t g_collo[NPIX*PITCH];     // sampled cols lo

// ===========================================================================
// Helpers (baseline PTX: ldmatrix + mma.sync + cp.async)
// ===========================================================================
__device__ __forceinline__ uint32_t smem_u32(const void* p) {
    uint32_t a;
    asm("{ .reg .u64 t; cvta.to.shared.u64 t, %1; cvt.u32.u64 %0, t; }"
        : "=r"(a) : "l"(p));
    return a;
}
__device__ __forceinline__ void ldsm4(uint32_t* r, uint32_t addr) {
    asm volatile("ldmatrix.sync.aligned.m8n8.x4.shared.b16 {%0,%1,%2,%3}, [%4];"
        : "=r"(r[0]), "=r"(r[1]), "=r"(r[2]), "=r"(r[3]) : "r"(addr));
}
__device__ __forceinline__ void ldsm2(uint32_t* r, uint32_t addr) {
    asm volatile("ldmatrix.sync.aligned.m8n8.x2.shared.b16 {%0,%1}, [%2];"
        : "=r"(r[0]), "=r"(r[1]) : "r"(addr));
}
__device__ __forceinline__ void mma16816(float* c, const uint32_t* a, const uint32_t* b) {
    asm volatile(
        "mma.sync.aligned.m16n8k16.row.col.f32.bf16.bf16.f32 "
        "{%0,%1,%2,%3}, {%4,%5,%6,%7}, {%8,%9}, {%0,%1,%2,%3};"
        : "+f"(c[0]), "+f"(c[1]), "+f"(c[2]), "+f"(c[3])
        : "r"(a[0]), "r"(a[1]), "r"(a[2]), "r"(a[3]), "r"(b[0]), "r"(b[1]));
}
#define CP_A16(dst, src) \
    asm volatile("cp.async.cg.shared.global [%0], [%1], 16;" \
                 :: "r"(dst), "l"(src))
#define CP_A16Z(dst, src, sz) \
    asm volatile("cp.async.cg.shared.global [%0], [%1], 16, %2;" \
                 :: "r"(dst), "l"(src), "r"(sz))
#define CP_COMMIT() asm volatile("cp.async.commit_group;")
#define CP_WAIT(n)  asm volatile("cp.async.wait_group %0;" :: "n"(n))

__device__ __forceinline__ uint32_t packbf(__nv_bfloat16 a, __nv_bfloat16 b) {
    __nv_bfloat162 t(a, b);
    return *(uint32_t*)&t;
}
__device__ __forceinline__ void split2(float v0, float v1, uint32_t& hi, uint32_t& lo) {
    __nv_bfloat16 h0 = __float2bfloat16(v0);
    __nv_bfloat16 h1 = __float2bfloat16(v1);
    __nv_bfloat16 l0 = __float2bfloat16(v0 - __bfloat162float(h0));
    __nv_bfloat16 l1 = __float2bfloat16(v1 - __bfloat162float(h1));
    hi = packbf(h0, h1);
    lo = packbf(l0, l1);
}

// ===========================================================================
// Kernel A: NCHW -> NHWC transpose + bf16 hi/lo split (smem tile, coalesced)
// ===========================================================================
__global__ void __launch_bounds__(256) transpose_kernel(const float* __restrict__ x) {
    __shared__ float ts[32][65];
    int bi  = blockIdx.x;
    int ct  = bi & 3;
    int rem = bi >> 2;
    int y   = rem & 63;
    int b   = rem >> 6;
    int c0  = ct * 32;
    int t   = threadIdx.x;

    #pragma unroll
    for (int it = 0; it < 8; it++) {
        int idx = it*256 + t;
        int cl = idx >> 6, xw = idx & 63;
        ts[cl][xw] = x[((b*C_ + c0 + cl)*H_ + y)*W_ + xw];
    }
    __syncthreads();
    #pragma unroll
    for (int it = 0; it < 8; it++) {
        int idx = it*256 + t;
        int cl = idx & 31, xw = idx >> 5;
        g_xT[((b*H_ + y)*W_ + xw)*C_ + c0 + cl] = ts[cl][xw];
    }
    #pragma unroll
    for (int it = 0; it < 4; it++) {
        int idx = it*256 + t;
        int cp = idx & 15, xw = idx >> 4;
        uint32_t hi, lo;
        split2(ts[cp*2][xw], ts[cp*2 + 1][xw], hi, lo);
        int o = ((b*H_ + y)*W_ + xw)*64 + (c0 >> 1) + cp;
        g_xhi[o] = hi;
        g_xlo[o] = lo;
    }
}

// ===========================================================================
// Kernel A2: main weight hi/lo split into [k2][oc][c] bf16x2
// ===========================================================================
__global__ void wsplit_kernel(const float* __restrict__ w) {
    int i2 = blockIdx.x * blockDim.x + threadIdx.x;
    if (i2 >= K2_*O_*C_/2) return;
    int cpair = i2 & 63;
    int oc    = (i2 >> 6) & 127;
    int k2    = i2 >> 13;
    int c = cpair * 2;
    uint32_t hi, lo;
    split2(w[oc*E_ + c*K2_ + k2], w[oc*E_ + (c+1)*K2_ + k2], hi, lo);
    g_whi[i2] = hi;
    g_wlo[i2] = lo;
}

// ===========================================================================
// Kernel A3: offset/mask weight pack
// ===========================================================================
__global__ void owpack_kernel(const float* __restrict__ offw,
                              const float* __restrict__ maskw) {
    int i2 = blockIdx.x * blockDim.x + threadIdx.x;
    if (i2 >= K2_*32*C_/2) return;
    int cp  = i2 & 63;
    int oc  = (i2 >> 6) & 31;
    int k2  = i2 >> 11;
    int c = cp * 2;
    float v0 = 0.f, v1 = 0.f;
    if (oc < 18) {
        v0 = offw[oc*E_ + c*K2_ + k2];
        v1 = offw[oc*E_ + (c+1)*K2_ + k2];
    } else if (oc < 27) {
        v0 = maskw[(oc-18)*E_ + c*K2_ + k2];
        v1 = maskw[(oc-18)*E_ + (c+1)*K2_ + k2];
    }
    uint32_t hi, lo;
    split2(v0, v1, hi, lo);
    g_owhi[i2] = hi;
    g_owlo[i2] = lo;
}

// ===========================================================================
// Kernel B: offset+mask conv via HMMA, cp.async double-buffered.
// Block = 64 pixels (1 row) x 32 oc, 256 threads, 2 blocks/SM. Grid 512.
// Warp tile 16 pix x 16 oc (warp grid 4x2). A row stride 272 B.
// ===========================================================================
#define OM_SLOT 52224
#define OM_A_HI 0
#define OM_A_LO 17408
#define OM_B_HI 34816
#define OM_B_LO 43520
#define OM_BIAS (2*OM_SLOT)          // 104448
#define OM_TOTAL (2*OM_SLOT + 128)   // 104576

__global__ void __launch_bounds__(256, 2) offmask_mma_kernel(
    const float* __restrict__ offb, const float* __restrict__ maskb) {
    extern __shared__ char smem[];
    uint32_t sb = smem_u32(smem);
    const int t    = threadIdx.x;
    const int lane = t & 31;
    const int wid  = t >> 5;        // 0..7
    const int bi   = blockIdx.x;    // 512
    const int b    = bi >> 6;
    const int row  = bi & 63;

    float* bias_s = (float*)(smem + OM_BIAS);
    if (t < 32)
        bias_s[t] = (t < 18) ? offb[t] : (t < 27 ? maskb[t-18] : 0.f);

    const int warp_m = wid >> 1;    // 4 groups of 16 pixels
    const int warp_n = wid & 1;     // 2 groups of 16 oc
    const uint32_t aOff = (uint32_t)((warp_m*16 + (lane & 15))*272 + (lane >> 4)*16);
    const uint32_t bOff = (uint32_t)((warp_n*16 + (lane & 7))*272 + ((lane >> 3) & 1)*16);

    float acc[2][4];
    #pragma unroll
    for (int i = 0; i < 2; i++)
        #pragma unroll
        for (int j = 0; j < 4; j++) acc[i][j] = 0.f;

    // A staging: 4 threads per pixel (quarters of the 64-u32 row)
    const int m   = t >> 2;         // pixel (col) 0..63
    const int q   = t & 3;          // quarter
    const int col = m;

    auto stage = [&](int k2) {
        uint32_t slot = (uint32_t)((k2 & 1) * OM_SLOT);
        // B chunk: 2048 u32 per buffer / 256 threads = 2 uint4 each
        #pragma unroll
        for (int it = 0; it < 2; it++) {
            int idx = it*256 + t;
            int oc = idx >> 4;
            int g  = idx & 15;
            int gi = k2*2048 + oc*64 + g*4;
            uint32_t so = slot + (uint32_t)(oc*272 + g*16);
            CP_A16(sb + OM_B_HI + so, &g_owhi[gi]);
            CP_A16(sb + OM_B_LO + so, &g_owlo[gi]);
        }
        // A chunk: im2col with zero-fill
        int ki = k2 / 3, kj = k2 - ki*3;
        int sy = row - 1 + ki;
        int sx = col - 1 + kj;
        bool valid = (sy >= 0) && (sy < H_) && (sx >= 0) && (sx < W_);
        uint32_t sz = valid ? 16u : 0u;
        int syc = valid ? sy : 0;
        int sxc = valid ? sx : 0;
        int gb = ((b*H_ + syc)*W_ + sxc)*64 + q*16;
        uint32_t abase = slot + (uint32_t)(m*272 + q*64);
        #pragma unroll
        for (int j4 = 0; j4 < 4; j4++) {
            CP_A16Z(sb + OM_A_HI + abase + j4*16, &g_xhi[gb + j4*4], sz);
            CP_A16Z(sb + OM_A_LO + abase + j4*16, &g_xlo[gb + j4*4], sz);
        }
        CP_COMMIT();
    };

    stage(0);
    for (int k2 = 0; k2 < K2_; k2++) {
        if (k2 < K2_-1) { stage(k2+1); CP_WAIT(1); }
        else           { CP_WAIT(0); }
        __syncthreads();

        uint32_t slot = (uint32_t)((k2 & 1) * OM_SLOT);
        #pragma unroll
        for (int pass = 0; pass < 3; pass++) {
            uint32_t ab = sb + slot + ((pass == 2) ? OM_A_LO : OM_A_HI) + aOff;
            uint32_t bb = sb + slot + ((pass == 1) ? OM_B_LO : OM_B_HI) + bOff;
            #pragma unroll
            for (int ks = 0; ks < 8; ks++) {
                uint32_t afr[4];
                ldsm4(afr, ab + ks*32);
                #pragma unroll
                for (int nt = 0; nt < 2; nt++) {
                    uint32_t bfr[2];
                    ldsm2(bfr, bb + nt*2176 + ks*32);
                    mma16816(acc[nt], afr, bfr);
                }
            }
        }
        __syncthreads();
    }

    // epilogue: bias + sigmoid, scatter
    const int r0  = lane >> 2;
    const int cl0 = (lane & 3)*2;
    #pragma unroll
    for (int nt = 0; nt < 2; nt++) {
        #pragma unroll
        for (int j = 0; j < 4; j++) {
            int oc = warp_n*16 + nt*8 + cl0 + (j & 1);
            if (oc >= 27) continue;
            int pcol = warp_m*16 + r0 + (j >> 1)*8;
            int gpix = (b*H_ + row)*W_ + pcol;
            float v = acc[nt][j] + bias_s[oc];
            if (oc >= 18) v = 1.f / (1.f + expf(-v));
            g_offmask[gpix*27 + oc] = v;
        }
    }
}

// ===========================================================================
// Kernel S: sample cols to gmem. One warp per (pixel, k2) task.
// ===========================================================================
__global__ void __launch_bounds__(256) sample_cols_kernel() {
    int task = blockIdx.x * 8 + (threadIdx.x >> 5);
    int lane = threadIdx.x & 31;
    int pix = task / 9;
    int k2  = task - pix*9;
    int b   = pix >> 12;
    int rem = pix & 4095;
    int row = rem >> 6;
    int col = rem & 63;

    float offy = g_offmask[pix*27 + 2*k2];
    float offx = g_offmask[pix*27 + 2*k2 + 1];
    float msk  = g_offmask[pix*27 + 18 + k2];
    int ki = k2 / 3, kj = k2 - ki*3;
    float py = (float)(row - 1 + ki) + offy;
    float px = (float)(col - 1 + kj) + offx;
    float y0f = floorf(py), x0f = floorf(px);
    float ly = py - y0f, lx = px - x0f;
    int y0 = (int)y0f, x0 = (int)x0f;
    float w00 = (1.f-ly)*(1.f-lx)*msk;
    float w01 = (1.f-ly)*lx*msk;
    float w10 = ly*(1.f-lx)*msk;
    float w11 = ly*lx*msk;
    bool vy0 = (y0 >= 0) && (y0 < H_);
    bool vy1 = (y0+1 >= 0) && (y0+1 < H_);
    bool vx0 = (x0 >= 0) && (x0 < W_);
    bool vx1 = (x0+1 >= 0) && (x0+1 < W_);
    bool p00 = vy0 && vx0, p01 = vy0 && vx1;
    bool p10 = vy1 && vx0, p11 = vy1 && vx1;
    const float4* xb4 = (const float4*)g_xT + (size_t)b * H_ * W_ * 32;
    int i00 = (y0*W_ + x0)*32 + lane;
    float4 zero = make_float4(0.f, 0.f, 0.f, 0.f);
    float4 v00 = p00 ? xb4[i00           ] : zero;
    float4 v01 = p01 ? xb4[i00 + 32      ] : zero;
    float4 v10 = p10 ? xb4[i00 + W_*32   ] : zero;
    float4 v11 = p11 ? xb4[i00 + W_*32+32] : zero;
    float r0 = w00*v00.x + w01*v01.x + w10*v10.x + w11*v11.x;
    float r1 = w00*v00.y + w01*v01.y + w10*v10.y + w11*v11.y;
    float r2 = w00*v00.z + w01*v01.z + w10*v10.z + w11*v11.z;
    float r3 = w00*v00.w + w01*v01.w + w10*v10.w + w11*v11.w;
    uint32_t hi01, lo01, hi23, lo23;
    split2(r0, r1, hi01, lo01);
    split2(r2, r3, hi23, lo23);
    int o = pix*PITCH + k2*64 + lane*2;
    *(uint2*)&g_colhi[o] = make_uint2(hi01, hi23);
    *(uint2*)&g_collo[o] = make_uint2(lo01, lo23);
}

// ===========================================================================
// Kernel C: pure GEMM, cp.async double-buffered.
// Block = 64 pix (1 row) x 128 oc, 256 threads, 2 blocks/SM. Grid 512.
// Warp tile 32 pix x 32 oc (warp grid 2x4). 18 K-subchunks of 64 channels.
// ===========================================================================
#define G_SLOT 55296
#define G_A_HI 0
#define G_A_LO 9216
#define G_W_HI 18432
#define G_W_LO 36864
#define G_TOTAL (2*G_SLOT)    // 110592

__global__ void __launch_bounds__(256, 2) dcn_gemm_kernel(float* __restrict__ out) {
    extern __shared__ char smem[];
    uint32_t sb = smem_u32(smem);
    const int t    = threadIdx.x;
    const int lane = t & 31;
    const int wid  = t >> 5;        // 0..7
    const int bi   = blockIdx.x;    // 512 blocks, pixels [bi*64, bi*64+64)
    const int b    = bi >> 6;
    const int row  = bi & 63;

    const int warp_m = wid & 1;     // 2 groups of 32 pixels
    const int warp_n = wid >> 1;    // 4 groups of 32 oc
    const uint32_t a_off = (uint32_t)((warp_m*32 + (lane & 15))*144 + (lane >> 4)*16);
    const uint32_t b_off = (uint32_t)((warp_n*32 + (lane & 7))*144 + ((lane >> 3) & 1)*16);

    float acc[2][4][4];
    #pragma unroll
    for (int i = 0; i < 2; i++)
        #pragma unroll
        for (int j = 0; j < 4; j++)
            #pragma unroll
            for (int k = 0; k < 4; k++) acc[i][j][k] = 0.f;

    // A staging: 4 threads per pixel (quarters of the 32-u32 sub-row)
    const int sp = t >> 2;          // pixel 0..63
    const int sq = t & 3;
    const int gA = (bi*64 + sp) * PITCH + sq*8;

    auto stage = [&](int sub) {
        uint32_t slot = (uint32_t)((sub & 1) * G_SLOT);
        uint32_t aso = slot + (uint32_t)(sp*144 + sq*32);
        int gsrc = gA + sub*32;
        #pragma unroll
        for (int j = 0; j < 2; j++) {
            CP_A16(sb + G_A_HI + aso + j*16, &g_colhi[gsrc + j*4]);
            CP_A16(sb + G_A_LO + aso + j*16, &g_collo[gsrc + j*4]);
        }
        int k2 = sub >> 1, ch = sub & 1;
        #pragma unroll
        for (int it = 0; it < 4; it++) {
            int idx = it*256 + t;           // 0..1023
            int oc = idx >> 3;
            int g  = idx & 7;
            int gi = k2*8192 + oc*64 + ch*32 + g*4;
            uint32_t so = slot + (uint32_t)(oc*144 + g*16);
            CP_A16(sb + G_W_HI + so, &g_whi[gi]);
            CP_A16(sb + G_W_LO + so, &g_wlo[gi]);
        }
        CP_COMMIT();
    };

    stage(0);
    for (int sub = 0; sub < 18; sub++) {
        if (sub < 17) { stage(sub+1); CP_WAIT(1); }
        else          { CP_WAIT(0); }
        __syncthreads();

        uint32_t slot = (uint32_t)((sub & 1) * G_SLOT);
        #pragma unroll
        for (int pass = 0; pass < 3; pass++) {
            uint32_t ab = sb + slot + ((pass == 2) ? G_A_LO : G_A_HI) + a_off;
            uint32_t bb = sb + slot + ((pass == 1) ? G_W_LO : G_W_HI) + b_off;
            #pragma unroll
            for (int ks = 0; ks < 4; ks++) {
                uint32_t afr[2][4];
                uint32_t bfr[4][2];
                #pragma unroll
                for (int mt = 0; mt < 2; mt++)
                    ldsm4(afr[mt], ab + mt*2304 + ks*32);
                #pragma unroll
                for (int nt = 0; nt < 4; nt++)
                    ldsm2(bfr[nt], bb + nt*1152 + ks*32);
                #pragma unroll
                for (int mt = 0; mt < 2; mt++)
                    #pragma unroll
                    for (int nt = 0; nt < 4; nt++)
                        mma16816(acc[mt][nt], afr[mt], bfr[nt]);
            }
        }
        __syncthreads();
    }

    // ---- epilogue: transpose through smem, coalesced NCHW stores ----
    float* O_s = (float*)smem;     // [oc][pix 64], stride 68 (34816 B)
    const int g   = lane >> 2;
    const int tig = lane & 3;
    #pragma unroll
    for (int mt = 0; mt < 2; mt++) {
        #pragma unroll
        for (int nt = 0; nt < 4; nt++) {
            int p0 = warp_m*32 + mt*16 + g;
            int o0 = warp_n*32 + nt*8 + tig*2;
            O_s[(o0  )*68 + p0    ] = acc[mt][nt][0];
            O_s[(o0+1)*68 + p0    ] = acc[mt][nt][1];
            O_s[(o0  )*68 + p0 + 8] = acc[mt][nt][2];
            O_s[(o0+1)*68 + p0 + 8] = acc[mt][nt][3];
        }
    }
    __syncthreads();
    // 128 oc x 64 pix = 8192 / 256 = 32 iterations
    #pragma unroll 4
    for (int it = 0; it < 32; it++) {
        int idx = it*256 + t;
        int oc = idx >> 6;
        int p  = idx & 63;
        out[(((size_t)b*O_ + oc)*H_ + row)*W_ + p] = O_s[oc*68 + p];
    }
}

// ===========================================================================
extern "C" void kernel_launch(void* const* d_in, const int* in_sizes, int n_in,
                              void* d_out, int out_size) {
    const float* x      = (const float*)d_in[0];
    const float* weight = (const float*)d_in[1];
    const float* offw   = (const float*)d_in[2];
    const float* offb   = (const float*)d_in[3];
    const float* maskw  = (const float*)d_in[4];
    const float* maskb  = (const float*)d_in[5];
    float* out = (float*)d_out;

    static bool attr_set = false;
    if (!attr_set) {
        cudaFuncSetAttribute(offmask_mma_kernel,
            cudaFuncAttributeMaxDynamicSharedMemorySize, OM_TOTAL);
        cudaFuncSetAttribute(dcn_gemm_kernel,
            cudaFuncAttributeMaxDynamicSharedMemorySize, G_TOTAL);
        attr_set = true;
    }

    transpose_kernel<<<B_*H_*4, 256>>>(x);
    wsplit_kernel<<<(K2_*O_*C_/2 + 255)/256, 256>>>(weight);
    owpack_kernel<<<(K2_*32*C_/2 + 255)/256, 256>>>(offw, maskw);
    offmask_mma_kernel<<<512, 256, OM_TOTAL>>>(offb, maskb);
    sample_cols_kernel<<<NPIX*K2_/8, 256>>>();
    dcn_gemm_kernel<<<512, 256, G_TOTAL>>>(out);
}

// round 12
// speedup vs baseline: 4.3555x; 1.0037x over previous
#include <cuda_runtime.h>
#include <cuda_bf16.h>
#include <math.h>
#include <stdint.h>

// Problem constants
#define B_  8
#define C_  128
#define H_  64
#define W_  64
#define O_  128
#define K2_ 9
#define E_  1152   // C_*K2_
#define NPIX (B_*H_*W_)      // 32768
#define PITCH 576            // u32 per pixel row of cols (1152 bf16 / 2)

// Scratch (device globals; no allocation allowed)
__device__ float    g_xT [B_*H_*W_*C_];      // NHWC fp32
__device__ uint32_t g_xhi[B_*H_*W_*C_/2];    // NHWC bf16x2 hi split
__device__ uint32_t g_xlo[B_*H_*W_*C_/2];    // NHWC bf16x2 lo split
__device__ float    g_offmask[NPIX*27];      // 18 offsets + 9 sigmoided masks / pixel
__device__ uint32_t g_whi[K2_*O_*C_/2];      // main weight hi, [k2][oc][c/2]
__device__ uint32_t g_wlo[K2_*O_*C_/2];      // main weight lo
__device__ uint32_t g_owhi[K2_*32*C_/2];     // offset/mask weight hi
__device__ uint32_t g_owlo[K2_*32*C_/2];     // offset/mask weight lo
__device__ uint32_t g_colhi[NPIX*PITCH];     // sampled cols hi, [pix][k2][c/2]
__device__ uint32_t g_collo[NPIX*PITCH];     // sampled cols lo

// ===========================================================================
// Helpers (baseline PTX: ldmatrix + mma.sync + cp.async)
// ===========================================================================
__device__ __forceinline__ uint32_t smem_u32(const void* p) {
    uint32_t a;
    asm("{ .reg .u64 t; cvta.to.shared.u64 t, %1; cvt.u32.u64 %0, t; }"
        : "=r"(a) : "l"(p));
    return a;
}
__device__ __forceinline__ void ldsm4(uint32_t* r, uint32_t addr) {
    asm volatile("ldmatrix.sync.aligned.m8n8.x4.shared.b16 {%0,%1,%2,%3}, [%4];"
        : "=r"(r[0]), "=r"(r[1]), "=r"(r[2]), "=r"(r[3]) : "r"(addr));
}
__device__ __forceinline__ void ldsm2(uint32_t* r, uint32_t addr) {
    asm volatile("ldmatrix.sync.aligned.m8n8.x2.shared.b16 {%0,%1}, [%2];"
        : "=r"(r[0]), "=r"(r[1]) : "r"(addr));
}
__device__ __forceinline__ void mma16816(float* c, const uint32_t* a, const uint32_t* b) {
    asm volatile(
        "mma.sync.aligned.m16n8k16.row.col.f32.bf16.bf16.f32 "
        "{%0,%1,%2,%3}, {%4,%5,%6,%7}, {%8,%9}, {%0,%1,%2,%3};"
        : "+f"(c[0]), "+f"(c[1]), "+f"(c[2]), "+f"(c[3])
        : "r"(a[0]), "r"(a[1]), "r"(a[2]), "r"(a[3]), "r"(b[0]), "r"(b[1]));
}
#define CP_A16(dst, src) \
    asm volatile("cp.async.cg.shared.global [%0], [%1], 16;" \
                 :: "r"(dst), "l"(src))
#define CP_A16Z(dst, src, sz) \
    asm volatile("cp.async.cg.shared.global [%0], [%1], 16, %2;" \
                 :: "r"(dst), "l"(src), "r"(sz))
#define CP_COMMIT() asm volatile("cp.async.commit_group;")
#define CP_WAIT(n)  asm volatile("cp.async.wait_group %0;" :: "n"(n))

__device__ __forceinline__ uint32_t packbf(__nv_bfloat16 a, __nv_bfloat16 b) {
    __nv_bfloat162 t(a, b);
    return *(uint32_t*)&t;
}
__device__ __forceinline__ void split2(float v0, float v1, uint32_t& hi, uint32_t& lo) {
    __nv_bfloat16 h0 = __float2bfloat16(v0);
    __nv_bfloat16 h1 = __float2bfloat16(v1);
    __nv_bfloat16 l0 = __float2bfloat16(v0 - __bfloat162float(h0));
    __nv_bfloat16 l1 = __float2bfloat16(v1 - __bfloat162float(h1));
    hi = packbf(h0, h1);
    lo = packbf(l0, l1);
}

// ===========================================================================
// Kernel A: NCHW -> NHWC transpose + bf16 hi/lo split (smem tile, coalesced)
// ===========================================================================
__global__ void __launch_bounds__(256) transpose_kernel(const float* __restrict__ x) {
    __shared__ float ts[32][65];
    int bi  = blockIdx.x;
    int ct  = bi & 3;
    int rem = bi >> 2;
    int y   = rem & 63;
    int b   = rem >> 6;
    int c0  = ct * 32;
    int t   = threadIdx.x;

    #pragma unroll
    for (int it = 0; it < 8; it++) {
        int idx = it*256 + t;
        int cl = idx >> 6, xw = idx & 63;
        ts[cl][xw] = x[((b*C_ + c0 + cl)*H_ + y)*W_ + xw];
    }
    __syncthreads();
    #pragma unroll
    for (int it = 0; it < 8; it++) {
        int idx = it*256 + t;
        int cl = idx & 31, xw = idx >> 5;
        g_xT[((b*H_ + y)*W_ + xw)*C_ + c0 + cl] = ts[cl][xw];
    }
    #pragma unroll
    for (int it = 0; it < 4; it++) {
        int idx = it*256 + t;
        int cp = idx & 15, xw = idx >> 4;
        uint32_t hi, lo;
        split2(ts[cp*2][xw], ts[cp*2 + 1][xw], hi, lo);
        int o = ((b*H_ + y)*W_ + xw)*64 + (c0 >> 1) + cp;
        g_xhi[o] = hi;
        g_xlo[o] = lo;
    }
}

// ===========================================================================
// Kernel A2: main weight hi/lo split into [k2][oc][c] bf16x2
// ===========================================================================
__global__ void wsplit_kernel(const float* __restrict__ w) {
    int i2 = blockIdx.x * blockDim.x + threadIdx.x;
    if (i2 >= K2_*O_*C_/2) return;
    int cpair = i2 & 63;
    int oc    = (i2 >> 6) & 127;
    int k2    = i2 >> 13;
    int c = cpair * 2;
    uint32_t hi, lo;
    split2(w[oc*E_ + c*K2_ + k2], w[oc*E_ + (c+1)*K2_ + k2], hi, lo);
    g_whi[i2] = hi;
    g_wlo[i2] = lo;
}

// ===========================================================================
// Kernel A3: offset/mask weight pack
// ===========================================================================
__global__ void owpack_kernel(const float* __restrict__ offw,
                              const float* __restrict__ maskw) {
    int i2 = blockIdx.x * blockDim.x + threadIdx.x;
    if (i2 >= K2_*32*C_/2) return;
    int cp  = i2 & 63;
    int oc  = (i2 >> 6) & 31;
    int k2  = i2 >> 11;
    int c = cp * 2;
    float v0 = 0.f, v1 = 0.f;
    if (oc < 18) {
        v0 = offw[oc*E_ + c*K2_ + k2];
        v1 = offw[oc*E_ + (c+1)*K2_ + k2];
    } else if (oc < 27) {
        v0 = maskw[(oc-18)*E_ + c*K2_ + k2];
        v1 = maskw[(oc-18)*E_ + (c+1)*K2_ + k2];
    }
    uint32_t hi, lo;
    split2(v0, v1, hi, lo);
    g_owhi[i2] = hi;
    g_owlo[i2] = lo;
}

// ===========================================================================
// Kernel B: offset+mask conv via HMMA, cp.async double-buffered,
// software-pipelined LDSM->MMA. Block = 64 pix x 32 oc, 256 thr, 2 blk/SM.
// ===========================================================================
#define OM_SLOT 52224
#define OM_A_HI 0
#define OM_A_LO 17408
#define OM_B_HI 34816
#define OM_B_LO 43520
#define OM_BIAS (2*OM_SLOT)          // 104448
#define OM_TOTAL (2*OM_SLOT + 128)   // 104576

__global__ void __launch_bounds__(256, 2) offmask_mma_kernel(
    const float* __restrict__ offb, const float* __restrict__ maskb) {
    extern __shared__ char smem[];
    uint32_t sb = smem_u32(smem);
    const int t    = threadIdx.x;
    const int lane = t & 31;
    const int wid  = t >> 5;        // 0..7
    const int bi   = blockIdx.x;    // 512
    const int b    = bi >> 6;
    const int row  = bi & 63;

    float* bias_s = (float*)(smem + OM_BIAS);
    if (t < 32)
        bias_s[t] = (t < 18) ? offb[t] : (t < 27 ? maskb[t-18] : 0.f);

    const int warp_m = wid >> 1;    // 4 groups of 16 pixels
    const int warp_n = wid & 1;     // 2 groups of 16 oc
    const uint32_t aOff = (uint32_t)((warp_m*16 + (lane & 15))*272 + (lane >> 4)*16);
    const uint32_t bOff = (uint32_t)((warp_n*16 + (lane & 7))*272 + ((lane >> 3) & 1)*16);

    float acc[2][4];
    #pragma unroll
    for (int i = 0; i < 2; i++)
        #pragma unroll
        for (int j = 0; j < 4; j++) acc[i][j] = 0.f;

    // A staging: 4 threads per pixel (quarters of the 64-u32 row)
    const int m   = t >> 2;         // pixel (col) 0..63
    const int q   = t & 3;          // quarter
    const int col = m;

    auto stage = [&](int k2) {
        uint32_t slot = (uint32_t)((k2 & 1) * OM_SLOT);
        #pragma unroll
        for (int it = 0; it < 2; it++) {
            int idx = it*256 + t;
            int oc = idx >> 4;
            int g  = idx & 15;
            int gi = k2*2048 + oc*64 + g*4;
            uint32_t so = slot + (uint32_t)(oc*272 + g*16);
            CP_A16(sb + OM_B_HI + so, &g_owhi[gi]);
            CP_A16(sb + OM_B_LO + so, &g_owlo[gi]);
        }
        int ki = k2 / 3, kj = k2 - ki*3;
        int sy = row - 1 + ki;
        int sx = col - 1 + kj;
        bool valid = (sy >= 0) && (sy < H_) && (sx >= 0) && (sx < W_);
        uint32_t sz = valid ? 16u : 0u;
        int syc = valid ? sy : 0;
        int sxc = valid ? sx : 0;
        int gb = ((b*H_ + syc)*W_ + sxc)*64 + q*16;
        uint32_t abase = slot + (uint32_t)(m*272 + q*64);
        #pragma unroll
        for (int j4 = 0; j4 < 4; j4++) {
            CP_A16Z(sb + OM_A_HI + abase + j4*16, &g_xhi[gb + j4*4], sz);
            CP_A16Z(sb + OM_A_LO + abase + j4*16, &g_xlo[gb + j4*4], sz);
        }
        CP_COMMIT();
    };

    stage(0);
    for (int k2 = 0; k2 < K2_; k2++) {
        if (k2 < K2_-1) { stage(k2+1); CP_WAIT(1); }
        else           { CP_WAIT(0); }
        __syncthreads();

        uint32_t slot = (uint32_t)((k2 & 1) * OM_SLOT);

        // ---- software-pipelined MMA: 24 steps (3 passes x 8 ksteps) ----
        uint32_t afr[2][4];
        uint32_t bfr[2][2][2];
        auto ldf = [&](int s, int buf) {
            int pass = s >> 3, ks = s & 7;
            uint32_t ab = sb + slot + ((pass == 2) ? OM_A_LO : OM_A_HI) + aOff + ks*32;
            uint32_t bb = sb + slot + ((pass == 1) ? OM_B_LO : OM_B_HI) + bOff + ks*32;
            ldsm4(afr[buf], ab);
            ldsm2(bfr[buf][0], bb);
            ldsm2(bfr[buf][1], bb + 2176);
        };
        ldf(0, 0);
        #pragma unroll
        for (int s = 0; s < 24; s++) {
            if (s < 23) ldf(s+1, (s+1)&1);
            int bu = s & 1;
            mma16816(acc[0], afr[bu], bfr[bu][0]);
            mma16816(acc[1], afr[bu], bfr[bu][1]);
        }
        __syncthreads();
    }

    // epilogue: bias + sigmoid, scatter
    const int r0  = lane >> 2;
    const int cl0 = (lane & 3)*2;
    #pragma unroll
    for (int nt = 0; nt < 2; nt++) {
        #pragma unroll
        for (int j = 0; j < 4; j++) {
            int oc = warp_n*16 + nt*8 + cl0 + (j & 1);
            if (oc >= 27) continue;
            int pcol = warp_m*16 + r0 + (j >> 1)*8;
            int gpix = (b*H_ + row)*W_ + pcol;
            float v = acc[nt][j] + bias_s[oc];
            if (oc >= 18) v = 1.f / (1.f + expf(-v));
            g_offmask[gpix*27 + oc] = v;
        }
    }
}

// ===========================================================================
// Kernel S: sample cols to gmem. One warp per (pixel, k2) task.
// ===========================================================================
__global__ void __launch_bounds__(256) sample_cols_kernel() {
    int task = blockIdx.x * 8 + (threadIdx.x >> 5);
    int lane = threadIdx.x & 31;
    int pix = task / 9;
    int k2  = task - pix*9;
    int b   = pix >> 12;
    int rem = pix & 4095;
    int row = rem >> 6;
    int col = rem & 63;

    float offy = g_offmask[pix*27 + 2*k2];
    float offx = g_offmask[pix*27 + 2*k2 + 1];
    float msk  = g_offmask[pix*27 + 18 + k2];
    int ki = k2 / 3, kj = k2 - ki*3;
    float py = (float)(row - 1 + ki) + offy;
    float px = (float)(col - 1 + kj) + offx;
    float y0f = floorf(py), x0f = floorf(px);
    float ly = py - y0f, lx = px - x0f;
    int y0 = (int)y0f, x0 = (int)x0f;
    float w00 = (1.f-ly)*(1.f-lx)*msk;
    float w01 = (1.f-ly)*lx*msk;
    float w10 = ly*(1.f-lx)*msk;
    float w11 = ly*lx*msk;
    bool vy0 = (y0 >= 0) && (y0 < H_);
    bool vy1 = (y0+1 >= 0) && (y0+1 < H_);
    bool vx0 = (x0 >= 0) && (x0 < W_);
    bool vx1 = (x0+1 >= 0) && (x0+1 < W_);
    bool p00 = vy0 && vx0, p01 = vy0 && vx1;
    bool p10 = vy1 && vx0, p11 = vy1 && vx1;
    const float4* xb4 = (const float4*)g_xT + (size_t)b * H_ * W_ * 32;
    int i00 = (y0*W_ + x0)*32 + lane;
    float4 zero = make_float4(0.f, 0.f, 0.f, 0.f);
    float4 v00 = p00 ? xb4[i00           ] : zero;
    float4 v01 = p01 ? xb4[i00 + 32      ] : zero;
    float4 v10 = p10 ? xb4[i00 + W_*32   ] : zero;
    float4 v11 = p11 ? xb4[i00 + W_*32+32] : zero;
    float r0 = w00*v00.x + w01*v01.x + w10*v10.x + w11*v11.x;
    float r1 = w00*v00.y + w01*v01.y + w10*v10.y + w11*v11.y;
    float r2 = w00*v00.z + w01*v01.z + w10*v10.z + w11*v11.z;
    float r3 = w00*v00.w + w01*v01.w + w10*v10.w + w11*v11.w;
    uint32_t hi01, lo01, hi23, lo23;
    split2(r0, r1, hi01, lo01);
    split2(r2, r3, hi23, lo23);
    int o = pix*PITCH + k2*64 + lane*2;
    *(uint2*)&g_colhi[o] = make_uint2(hi01, hi23);
    *(uint2*)&g_collo[o] = make_uint2(lo01, lo23);
}

// ===========================================================================
// Kernel C: pure GEMM, cp.async double-buffered, software-pipelined LDSM.
// Block = 64 pix (1 row) x 128 oc, 256 threads, 2 blocks/SM. Grid 512.
// Warp tile 32 pix x 32 oc (warp grid 2x4). 18 K-subchunks of 64 channels.
// ===========================================================================
#define G_SLOT 55296
#define G_A_HI 0
#define G_A_LO 9216
#define G_W_HI 18432
#define G_W_LO 36864
#define G_TOTAL (2*G_SLOT)    // 110592

__global__ void __launch_bounds__(256, 2) dcn_gemm_kernel(float* __restrict__ out) {
    extern __shared__ char smem[];
    uint32_t sb = smem_u32(smem);
    const int t    = threadIdx.x;
    const int lane = t & 31;
    const int wid  = t >> 5;        // 0..7
    const int bi   = blockIdx.x;    // 512 blocks, pixels [bi*64, bi*64+64)
    const int b    = bi >> 6;
    const int row  = bi & 63;

    const int warp_m = wid & 1;     // 2 groups of 32 pixels
    const int warp_n = wid >> 1;    // 4 groups of 32 oc
    const uint32_t a_off = (uint32_t)((warp_m*32 + (lane & 15))*144 + (lane >> 4)*16);
    const uint32_t b_off = (uint32_t)((warp_n*32 + (lane & 7))*144 + ((lane >> 3) & 1)*16);

    float acc[2][4][4];
    #pragma unroll
    for (int i = 0; i < 2; i++)
        #pragma unroll
        for (int j = 0; j < 4; j++)
            #pragma unroll
            for (int k = 0; k < 4; k++) acc[i][j][k] = 0.f;

    // A staging: 4 threads per pixel (quarters of the 32-u32 sub-row)
    const int sp = t >> 2;          // pixel 0..63
    const int sq = t & 3;
    const int gA = (bi*64 + sp) * PITCH + sq*8;

    auto stage = [&](int sub) {
        uint32_t slot = (uint32_t)((sub & 1) * G_SLOT);
        uint32_t aso = slot + (uint32_t)(sp*144 + sq*32);
        int gsrc = gA + sub*32;
        #pragma unroll
        for (int j = 0; j < 2; j++) {
            CP_A16(sb + G_A_HI + aso + j*16, &g_colhi[gsrc + j*4]);
            CP_A16(sb + G_A_LO + aso + j*16, &g_collo[gsrc + j*4]);
        }
        int k2 = sub >> 1, ch = sub & 1;
        #pragma unroll
        for (int it = 0; it < 4; it++) {
            int idx = it*256 + t;           // 0..1023
            int oc = idx >> 3;
            int g  = idx & 7;
            int gi = k2*8192 + oc*64 + ch*32 + g*4;
            uint32_t so = slot + (uint32_t)(oc*144 + g*16);
            CP_A16(sb + G_W_HI + so, &g_whi[gi]);
            CP_A16(sb + G_W_LO + so, &g_wlo[gi]);
        }
        CP_COMMIT();
    };

    stage(0);
    for (int sub = 0; sub < 18; sub++) {
        if (sub < 17) { stage(sub+1); CP_WAIT(1); }
        else          { CP_WAIT(0); }
        __syncthreads();

        uint32_t slot = (uint32_t)((sub & 1) * G_SLOT);

        // ---- software-pipelined MMA: 12 steps (3 passes x 4 ksteps) ----
        uint32_t afr[2][2][4];
        uint32_t bfr[2][4][2];
        auto ldf = [&](int s, int buf) {
            int pass = s >> 2, ks = s & 3;
            uint32_t ab = sb + slot + ((pass == 2) ? G_A_LO : G_A_HI) + a_off + ks*32;
            uint32_t bb = sb + slot + ((pass == 1) ? G_W_LO : G_W_HI) + b_off + ks*32;
            ldsm4(afr[buf][0], ab);
            ldsm4(afr[buf][1], ab + 2304);
            ldsm2(bfr[buf][0], bb);
            ldsm2(bfr[buf][1], bb + 1152);
            ldsm2(bfr[buf][2], bb + 2304);
            ldsm2(bfr[buf][3], bb + 3456);
        };
        ldf(0, 0);
        #pragma unroll
        for (int s = 0; s < 12; s++) {
            if (s < 11) ldf(s+1, (s+1)&1);
            int bu = s & 1;
            #pragma unroll
            for (int mt = 0; mt < 2; mt++)
                #pragma unroll
                for (int nt = 0; nt < 4; nt++)
                    mma16816(acc[mt][nt], afr[bu][mt], bfr[bu][nt]);
        }
        __syncthreads();
    }

    // ---- epilogue: transpose through smem, coalesced NCHW stores ----
    float* O_s = (float*)smem;     // [oc][pix 64], stride 68 (34816 B)
    const int g   = lane >> 2;
    const int tig = lane & 3;
    #pragma unroll
    for (int mt = 0; mt < 2; mt++) {
        #pragma unroll
        for (int nt = 0; nt < 4; nt++) {
            int p0 = warp_m*32 + mt*16 + g;
            int o0 = warp_n*32 + nt*8 + tig*2;
            O_s[(o0  )*68 + p0    ] = acc[mt][nt][0];
            O_s[(o0+1)*68 + p0    ] = acc[mt][nt][1];
            O_s[(o0  )*68 + p0 + 8] = acc[mt][nt][2];
            O_s[(o0+1)*68 + p0 + 8] = acc[mt][nt][3];
        }
    }
    __syncthreads();
    // 128 oc x 64 pix = 8192 / 256 = 32 iterations
    #pragma unroll 4
    for (int it = 0; it < 32; it++) {
        int idx = it*256 + t;
        int oc = idx >> 6;
        int p  = idx & 63;
        out[(((size_t)b*O_ + oc)*H_ + row)*W_ + p] = O_s[oc*68 + p];
    }
}

// ===========================================================================
extern "C" void kernel_launch(void* const* d_in, const int* in_sizes, int n_in,
                              void* d_out, int out_size) {
    const float* x      = (const float*)d_in[0];
    const float* weight = (const float*)d_in[1];
    const float* offw   = (const float*)d_in[2];
    const float* offb   = (const float*)d_in[3];
    const float* maskw  = (const float*)d_in[4];
    const float* maskb  = (const float*)d_in[5];
    float* out = (float*)d_out;

    static bool attr_set = false;
    if (!attr_set) {
        cudaFuncSetAttribute(offmask_mma_kernel,
            cudaFuncAttributeMaxDynamicSharedMemorySize, OM_TOTAL);
        cudaFuncSetAttribute(dcn_gemm_kernel,
            cudaFuncAttributeMaxDynamicSharedMemorySize, G_TOTAL);
        attr_set = true;
    }

    transpose_kernel<<<B_*H_*4, 256>>>(x);
    wsplit_kernel<<<(K2_*O_*C_/2 + 255)/256, 256>>>(weight);
    owpack_kernel<<<(K2_*32*C_/2 + 255)/256, 256>>>(offw, maskw);
    offmask_mma_kernel<<<512, 256, OM_TOTAL>>>(offb, maskb);
    sample_cols_kernel<<<NPIX*K2_/8, 256>>>();
    dcn_gemm_kernel<<<512, 256, G_TOTAL>>>(out);
}

// round 13
// speedup vs baseline: 7.3207x; 1.6808x over previous
#include <cuda_runtime.h>
#include <cuda_fp16.h>
#include <math.h>
#include <stdint.h>

// Problem constants
#define B_  8
#define C_  128
#define H_  64
#define W_  64
#define O_  128
#define K2_ 9
#define E_  1152   // C_*K2_
#define NPIX (B_*H_*W_)      // 32768
#define PITCH 576            // u32 per pixel row of cols (1152 fp16 / 2)

// Scratch (device globals; no allocation allowed)
__device__ float    g_xT [B_*H_*W_*C_];      // NHWC fp32 (for bilinear sampling)
__device__ uint32_t g_xh [B_*H_*W_*C_/2];    // NHWC fp16x2
__device__ float    g_offmask[NPIX*27];      // 18 offsets + 9 sigmoided masks / pixel
__device__ uint32_t g_wh [K2_*O_*C_/2];      // main weight fp16x2, [k2][oc][c/2]
__device__ uint32_t g_owh[K2_*32*C_/2];      // offset/mask weight fp16x2
__device__ uint32_t g_colh[NPIX*PITCH];      // sampled cols fp16x2, [pix][k2][c/2]

// ===========================================================================
// Helpers (baseline PTX: ldmatrix + mma.sync + cp.async)
// ===========================================================================
__device__ __forceinline__ uint32_t smem_u32(const void* p) {
    uint32_t a;
    asm("{ .reg .u64 t; cvta.to.shared.u64 t, %1; cvt.u32.u64 %0, t; }"
        : "=r"(a) : "l"(p));
    return a;
}
__device__ __forceinline__ void ldsm4(uint32_t* r, uint32_t addr) {
    asm volatile("ldmatrix.sync.aligned.m8n8.x4.shared.b16 {%0,%1,%2,%3}, [%4];"
        : "=r"(r[0]), "=r"(r[1]), "=r"(r[2]), "=r"(r[3]) : "r"(addr));
}
__device__ __forceinline__ void ldsm2(uint32_t* r, uint32_t addr) {
    asm volatile("ldmatrix.sync.aligned.m8n8.x2.shared.b16 {%0,%1}, [%2];"
        : "=r"(r[0]), "=r"(r[1]) : "r"(addr));
}
__device__ __forceinline__ void mma16816(float* c, const uint32_t* a, const uint32_t* b) {
    asm volatile(
        "mma.sync.aligned.m16n8k16.row.col.f32.f16.f16.f32 "
        "{%0,%1,%2,%3}, {%4,%5,%6,%7}, {%8,%9}, {%0,%1,%2,%3};"
        : "+f"(c[0]), "+f"(c[1]), "+f"(c[2]), "+f"(c[3])
        : "r"(a[0]), "r"(a[1]), "r"(a[2]), "r"(a[3]), "r"(b[0]), "r"(b[1]));
}
#define CP_A16(dst, src) \
    asm volatile("cp.async.cg.shared.global [%0], [%1], 16;" \
                 :: "r"(dst), "l"(src))
#define CP_A16Z(dst, src, sz) \
    asm volatile("cp.async.cg.shared.global [%0], [%1], 16, %2;" \
                 :: "r"(dst), "l"(src), "r"(sz))
#define CP_COMMIT() asm volatile("cp.async.commit_group;")
#define CP_WAIT(n)  asm volatile("cp.async.wait_group %0;" :: "n"(n))

__device__ __forceinline__ uint32_t f16pack(float a, float b) {
    __half2 h = __floats2half2_rn(a, b);
    return *(uint32_t*)&h;
}

// ===========================================================================
// Kernel A: NCHW -> NHWC transpose + fp16 convert (smem tile, coalesced)
// ===========================================================================
__global__ void __launch_bounds__(256) transpose_kernel(const float* __restrict__ x) {
    __shared__ float ts[32][65];
    int bi  = blockIdx.x;
    int ct  = bi & 3;
    int rem = bi >> 2;
    int y   = rem & 63;
    int b   = rem >> 6;
    int c0  = ct * 32;
    int t   = threadIdx.x;

    #pragma unroll
    for (int it = 0; it < 8; it++) {
        int idx = it*256 + t;
        int cl = idx >> 6, xw = idx & 63;
        ts[cl][xw] = x[((b*C_ + c0 + cl)*H_ + y)*W_ + xw];
    }
    __syncthreads();
    #pragma unroll
    for (int it = 0; it < 8; it++) {
        int idx = it*256 + t;
        int cl = idx & 31, xw = idx >> 5;
        g_xT[((b*H_ + y)*W_ + xw)*C_ + c0 + cl] = ts[cl][xw];
    }
    #pragma unroll
    for (int it = 0; it < 4; it++) {
        int idx = it*256 + t;
        int cp = idx & 15, xw = idx >> 4;
        int o = ((b*H_ + y)*W_ + xw)*64 + (c0 >> 1) + cp;
        g_xh[o] = f16pack(ts[cp*2][xw], ts[cp*2 + 1][xw]);
    }
}

// ===========================================================================
// Kernel A2: main weight fp16 pack into [k2][oc][c] fp16x2
// ===========================================================================
__global__ void wsplit_kernel(const float* __restrict__ w) {
    int i2 = blockIdx.x * blockDim.x + threadIdx.x;
    if (i2 >= K2_*O_*C_/2) return;
    int cpair = i2 & 63;
    int oc    = (i2 >> 6) & 127;
    int k2    = i2 >> 13;
    int c = cpair * 2;
    g_wh[i2] = f16pack(w[oc*E_ + c*K2_ + k2], w[oc*E_ + (c+1)*K2_ + k2]);
}

// ===========================================================================
// Kernel A3: offset/mask weight pack (oc 0..17 offw, 18..26 maskw, rest 0)
// ===========================================================================
__global__ void owpack_kernel(const float* __restrict__ offw,
                              const float* __restrict__ maskw) {
    int i2 = blockIdx.x * blockDim.x + threadIdx.x;
    if (i2 >= K2_*32*C_/2) return;
    int cp  = i2 & 63;
    int oc  = (i2 >> 6) & 31;
    int k2  = i2 >> 11;
    int c = cp * 2;
    float v0 = 0.f, v1 = 0.f;
    if (oc < 18) {
        v0 = offw[oc*E_ + c*K2_ + k2];
        v1 = offw[oc*E_ + (c+1)*K2_ + k2];
    } else if (oc < 27) {
        v0 = maskw[(oc-18)*E_ + c*K2_ + k2];
        v1 = maskw[(oc-18)*E_ + (c+1)*K2_ + k2];
    }
    g_owh[i2] = f16pack(v0, v1);
}

// ===========================================================================
// Kernel B: offset+mask conv via HMMA fp16, cp.async double-buffered.
// Block = 64 pix (1 row) x 32 oc, 256 threads, 2 blocks/SM. Grid 512.
// Warp tile 16 pix x 16 oc. A row stride 272 B.
// ===========================================================================
#define OM_SLOT 26112
#define OM_A 0
#define OM_B 17408
#define OM_BIAS (2*OM_SLOT)          // 52224
#define OM_TOTAL (2*OM_SLOT + 128)   // 52352

__global__ void __launch_bounds__(256, 2) offmask_mma_kernel(
    const float* __restrict__ offb, const float* __restrict__ maskb) {
    extern __shared__ char smem[];
    uint32_t sb = smem_u32(smem);
    const int t    = threadIdx.x;
    const int lane = t & 31;
    const int wid  = t >> 5;        // 0..7
    const int bi   = blockIdx.x;    // 512
    const int b    = bi >> 6;
    const int row  = bi & 63;

    float* bias_s = (float*)(smem + OM_BIAS);
    if (t < 32)
        bias_s[t] = (t < 18) ? offb[t] : (t < 27 ? maskb[t-18] : 0.f);

    const int warp_m = wid >> 1;    // 4 groups of 16 pixels
    const int warp_n = wid & 1;     // 2 groups of 16 oc
    const uint32_t aOff = (uint32_t)((warp_m*16 + (lane & 15))*272 + (lane >> 4)*16);
    const uint32_t bOff = (uint32_t)((warp_n*16 + (lane & 7))*272 + ((lane >> 3) & 1)*16);

    float acc[2][4];
    #pragma unroll
    for (int i = 0; i < 2; i++)
        #pragma unroll
        for (int j = 0; j < 4; j++) acc[i][j] = 0.f;

    // A staging: 4 threads per pixel (quarters of the 64-u32 row)
    const int m   = t >> 2;         // pixel (col) 0..63
    const int q   = t & 3;          // quarter
    const int col = m;

    auto stage = [&](int k2) {
        uint32_t slot = (uint32_t)((k2 & 1) * OM_SLOT);
        // B chunk: 2048 u32 / 256 threads = 2 x 16B each
        #pragma unroll
        for (int it = 0; it < 2; it++) {
            int idx = it*256 + t;
            int oc = idx >> 4;
            int g  = idx & 15;
            int gi = k2*2048 + oc*64 + g*4;
            uint32_t so = slot + (uint32_t)(oc*272 + g*16);
            CP_A16(sb + OM_B + so, &g_owh[gi]);
        }
        // A chunk: im2col with zero-fill
        int ki = k2 / 3, kj = k2 - ki*3;
        int sy = row - 1 + ki;
        int sx = col - 1 + kj;
        bool valid = (sy >= 0) && (sy < H_) && (sx >= 0) && (sx < W_);
        uint32_t sz = valid ? 16u : 0u;
        int syc = valid ? sy : 0;
        int sxc = valid ? sx : 0;
        int gb = ((b*H_ + syc)*W_ + sxc)*64 + q*16;
        uint32_t abase = slot + (uint32_t)(m*272 + q*64);
        #pragma unroll
        for (int j4 = 0; j4 < 4; j4++)
            CP_A16Z(sb + OM_A + abase + j4*16, &g_xh[gb + j4*4], sz);
        CP_COMMIT();
    };

    stage(0);
    for (int k2 = 0; k2 < K2_; k2++) {
        if (k2 < K2_-1) { stage(k2+1); CP_WAIT(1); }
        else           { CP_WAIT(0); }
        __syncthreads();

        uint32_t slot = (uint32_t)((k2 & 1) * OM_SLOT);

        // ---- software-pipelined MMA: 8 ksteps, single pass ----
        uint32_t afr[2][4];
        uint32_t bfr[2][2][2];
        auto ldf = [&](int ks, int buf) {
            uint32_t ab = sb + slot + OM_A + aOff + ks*32;
            uint32_t bb = sb + slot + OM_B + bOff + ks*32;
            ldsm4(afr[buf], ab);
            ldsm2(bfr[buf][0], bb);
            ldsm2(bfr[buf][1], bb + 2176);
        };
        ldf(0, 0);
        #pragma unroll
        for (int s = 0; s < 8; s++) {
            if (s < 7) ldf(s+1, (s+1)&1);
            int bu = s & 1;
            mma16816(acc[0], afr[bu], bfr[bu][0]);
            mma16816(acc[1], afr[bu], bfr[bu][1]);
        }
        __syncthreads();
    }

    // epilogue: bias + sigmoid, scatter
    const int r0  = lane >> 2;
    const int cl0 = (lane & 3)*2;
    #pragma unroll
    for (int nt = 0; nt < 2; nt++) {
        #pragma unroll
        for (int j = 0; j < 4; j++) {
            int oc = warp_n*16 + nt*8 + cl0 + (j & 1);
            if (oc >= 27) continue;
            int pcol = warp_m*16 + r0 + (j >> 1)*8;
            int gpix = (b*H_ + row)*W_ + pcol;
            float v = acc[nt][j] + bias_s[oc];
            if (oc >= 18) v = 1.f / (1.f + expf(-v));
            g_offmask[gpix*27 + oc] = v;
        }
    }
}

// ===========================================================================
// Kernel S: sample cols to gmem (fp16). One warp per (pixel, k2) task.
// ===========================================================================
__global__ void __launch_bounds__(256) sample_cols_kernel() {
    int task = blockIdx.x * 8 + (threadIdx.x >> 5);
    int lane = threadIdx.x & 31;
    int pix = task / 9;
    int k2  = task - pix*9;
    int b   = pix >> 12;
    int rem = pix & 4095;
    int row = rem >> 6;
    int col = rem & 63;

    float offy = g_offmask[pix*27 + 2*k2];
    float offx = g_offmask[pix*27 + 2*k2 + 1];
    float msk  = g_offmask[pix*27 + 18 + k2];
    int ki = k2 / 3, kj = k2 - ki*3;
    float py = (float)(row - 1 + ki) + offy;
    float px = (float)(col - 1 + kj) + offx;
    float y0f = floorf(py), x0f = floorf(px);
    float ly = py - y0f, lx = px - x0f;
    int y0 = (int)y0f, x0 = (int)x0f;
    float w00 = (1.f-ly)*(1.f-lx)*msk;
    float w01 = (1.f-ly)*lx*msk;
    float w10 = ly*(1.f-lx)*msk;
    float w11 = ly*lx*msk;
    bool vy0 = (y0 >= 0) && (y0 < H_);
    bool vy1 = (y0+1 >= 0) && (y0+1 < H_);
    bool vx0 = (x0 >= 0) && (x0 < W_);
    bool vx1 = (x0+1 >= 0) && (x0+1 < W_);
    bool p00 = vy0 && vx0, p01 = vy0 && vx1;
    bool p10 = vy1 && vx0, p11 = vy1 && vx1;
    const float4* xb4 = (const float4*)g_xT + (size_t)b * H_ * W_ * 32;
    int i00 = (y0*W_ + x0)*32 + lane;
    float4 zero = make_float4(0.f, 0.f, 0.f, 0.f);
    float4 v00 = p00 ? xb4[i00           ] : zero;
    float4 v01 = p01 ? xb4[i00 + 32      ] : zero;
    float4 v10 = p10 ? xb4[i00 + W_*32   ] : zero;
    float4 v11 = p11 ? xb4[i00 + W_*32+32] : zero;
    float r0 = w00*v00.x + w01*v01.x + w10*v10.x + w11*v11.x;
    float r1 = w00*v00.y + w01*v01.y + w10*v10.y + w11*v11.y;
    float r2 = w00*v00.z + w01*v01.z + w10*v10.z + w11*v11.z;
    float r3 = w00*v00.w + w01*v01.w + w10*v10.w + w11*v11.w;
    int o = pix*PITCH + k2*64 + lane*2;
    *(uint2*)&g_colh[o] = make_uint2(f16pack(r0, r1), f16pack(r2, r3));
}

// ===========================================================================
// Kernel C: pure GEMM fp16, cp.async double-buffered, software-pipelined.
// Block = 64 pix (1 row) x 128 oc, 256 threads, 2 blocks/SM. Grid 512.
// Warp tile 32 pix x 32 oc (warp grid 2x4). 18 K-subchunks of 64 channels.
// ===========================================================================
#define G_SLOT 27648
#define G_A 0
#define G_W 9216
#define G_TOTAL (2*G_SLOT)    // 55296

__global__ void __launch_bounds__(256, 2) dcn_gemm_kernel(float* __restrict__ out) {
    extern __shared__ char smem[];
    uint32_t sb = smem_u32(smem);
    const int t    = threadIdx.x;
    const int lane = t & 31;
    const int wid  = t >> 5;        // 0..7
    const int bi   = blockIdx.x;    // 512 blocks, pixels [bi*64, bi*64+64)
    const int b    = bi >> 6;
    const int row  = bi & 63;

    const int warp_m = wid & 1;     // 2 groups of 32 pixels
    const int warp_n = wid >> 1;    // 4 groups of 32 oc
    const uint32_t a_off = (uint32_t)((warp_m*32 + (lane & 15))*144 + (lane >> 4)*16);
    const uint32_t b_off = (uint32_t)((warp_n*32 + (lane & 7))*144 + ((lane >> 3) & 1)*16);

    float acc[2][4][4];
    #pragma unroll
    for (int i = 0; i < 2; i++)
        #pragma unroll
        for (int j = 0; j < 4; j++)
            #pragma unroll
            for (int k = 0; k < 4; k++) acc[i][j][k] = 0.f;

    // A staging: 4 threads per pixel (quarters of the 32-u32 sub-row)
    const int sp = t >> 2;          // pixel 0..63
    const int sq = t & 3;
    const int gA = (bi*64 + sp) * PITCH + sq*8;

    auto stage = [&](int sub) {
        uint32_t slot = (uint32_t)((sub & 1) * G_SLOT);
        uint32_t aso = slot + (uint32_t)(sp*144 + sq*32);
        int gsrc = gA + sub*32;
        #pragma unroll
        for (int j = 0; j < 2; j++)
            CP_A16(sb + G_A + aso + j*16, &g_colh[gsrc + j*4]);
        int k2 = sub >> 1, ch = sub & 1;
        #pragma unroll
        for (int it = 0; it < 4; it++) {
            int idx = it*256 + t;           // 0..1023
            int oc = idx >> 3;
            int g  = idx & 7;
            int gi = k2*8192 + oc*64 + ch*32 + g*4;
            uint32_t so = slot + (uint32_t)(oc*144 + g*16);
            CP_A16(sb + G_W + so, &g_wh[gi]);
        }
        CP_COMMIT();
    };

    stage(0);
    for (int sub = 0; sub < 18; sub++) {
        if (sub < 17) { stage(sub+1); CP_WAIT(1); }
        else          { CP_WAIT(0); }
        __syncthreads();

        uint32_t slot = (uint32_t)((sub & 1) * G_SLOT);

        // ---- software-pipelined MMA: 4 ksteps, single pass ----
        uint32_t afr[2][2][4];
        uint32_t bfr[2][4][2];
        auto ldf = [&](int ks, int buf) {
            uint32_t ab = sb + slot + G_A + a_off + ks*32;
            uint32_t bb = sb + slot + G_W + b_off + ks*32;
            ldsm4(afr[buf][0], ab);
            ldsm4(afr[buf][1], ab + 2304);
            ldsm2(bfr[buf][0], bb);
            ldsm2(bfr[buf][1], bb + 1152);
            ldsm2(bfr[buf][2], bb + 2304);
            ldsm2(bfr[buf][3], bb + 3456);
        };
        ldf(0, 0);
        #pragma unroll
        for (int s = 0; s < 4; s++) {
            if (s < 3) ldf(s+1, (s+1)&1);
            int bu = s & 1;
            #pragma unroll
            for (int mt = 0; mt < 2; mt++)
                #pragma unroll
                for (int nt = 0; nt < 4; nt++)
                    mma16816(acc[mt][nt], afr[bu][mt], bfr[bu][nt]);
        }
        __syncthreads();
    }

    // ---- epilogue: transpose through smem, coalesced NCHW stores ----
    float* O_s = (float*)smem;     // [oc][pix 64], stride 68 (34816 B < 55296)
    const int g   = lane >> 2;
    const int tig = lane & 3;
    #pragma unroll
    for (int mt = 0; mt < 2; mt++) {
        #pragma unroll
        for (int nt = 0; nt < 4; nt++) {
            int p0 = warp_m*32 + mt*16 + g;
            int o0 = warp_n*32 + nt*8 + tig*2;
            O_s[(o0  )*68 + p0    ] = acc[mt][nt][0];
            O_s[(o0+1)*68 + p0    ] = acc[mt][nt][1];
            O_s[(o0  )*68 + p0 + 8] = acc[mt][nt][2];
            O_s[(o0+1)*68 + p0 + 8] = acc[mt][nt][3];
        }
    }
    __syncthreads();
    // 128 oc x 64 pix = 8192 / 256 = 32 iterations
    #pragma unroll 4
    for (int it = 0; it < 32; it++) {
        int idx = it*256 + t;
        int oc = idx >> 6;
        int p  = idx & 63;
        out[(((size_t)b*O_ + oc)*H_ + row)*W_ + p] = O_s[oc*68 + p];
    }
}

// ===========================================================================
extern "C" void kernel_launch(void* const* d_in, const int* in_sizes, int n_in,
                              void* d_out, int out_size) {
    const float* x      = (const float*)d_in[0];
    const float* weight = (const float*)d_in[1];
    const float* offw   = (const float*)d_in[2];
    const float* offb   = (const float*)d_in[3];
    const float* maskw  = (const float*)d_in[4];
    const float* maskb  = (const float*)d_in[5];
    float* out = (float*)d_out;

    static bool attr_set = false;
    if (!attr_set) {
        cudaFuncSetAttribute(offmask_mma_kernel,
            cudaFuncAttributeMaxDynamicSharedMemorySize, OM_TOTAL);
        cudaFuncSetAttribute(dcn_gemm_kernel,
            cudaFuncAttributeMaxDynamicSharedMemorySize, G_TOTAL);
        attr_set = true;
    }

    transpose_kernel<<<B_*H_*4, 256>>>(x);
    wsplit_kernel<<<(K2_*O_*C_/2 + 255)/256, 256>>>(weight);
    owpack_kernel<<<(K2_*32*C_/2 + 255)/256, 256>>>(offw, maskw);
    offmask_mma_kernel<<<512, 256, OM_TOTAL>>>(offb, maskb);
    sample_cols_kernel<<<NPIX*K2_/8, 256>>>();
    dcn_gemm_kernel<<<512, 256, G_TOTAL>>>(out);
}